// round 4
// baseline (speedup 1.0000x reference)
#include <cuda_runtime.h>
#include <math.h>

#define Bb   16
#define Nn   1024
#define Dd   512
#define Hh   256
#define Mrows (Bb*Nn)   // 16384

// ---------------- scratch (static device globals; no allocation) ----------------
__device__ float g_tp[Mrows*Dd];      // tanh(x@tp_w+b)
__device__ float g_tc[Mrows*Dd];      // tanh(x@tc_w+b)
__device__ float g_u [Mrows*Dd];      // tp@bil_w
__device__ float g_h [Mrows*Dd];      // concat(g1,g2)+x
__device__ float g_y [Mrows*Hh];      // Y buffer (reused for both layers)
__device__ float g_g1[Mrows*Hh];
__device__ float g_g2[Mrows*Hh];
__device__ float g_f [Mrows];         // exp(x@fi_w)
__device__ float g_sv[Mrows];         // s scores
__device__ float g_a [Mrows];         // exp(s - smax_b)
__device__ float g_S [Bb];
__device__ float g_Q [Bb];
__device__ float g_pq[2*Bb*Hh];       // p then q

// ---------------- generic SGEMM: C[M,N] = act(A[M,K] @ B[K,N] (+C) (+bias)) ----
// flags: bit0 = tanh epilogue, bit1 = accumulate into existing C
// Requires: M%128==0, N%128==0, K%8==0 (true for all calls here).
__global__ __launch_bounds__(256) void sgemm_kernel(
    const float* __restrict__ A, const float* __restrict__ B,
    const float* __restrict__ bias, float* __restrict__ C,
    int M, int N, int K, int flags)
{
    const int BM = 128, BN = 128, BK = 8, TM = 8, TN = 8;
    __shared__ float As[BK][BM];
    __shared__ float Bs[BK][BN];

    const int tid  = threadIdx.x;
    const int brow = blockIdx.y;
    const int bcol = blockIdx.x;

    A += (size_t)brow * BM * K;
    B += (size_t)bcol * BN;

    const int arow  = tid >> 1;          // 0..127
    const int acol4 = (tid & 1) * 4;     // 0 or 4
    const int brw   = tid >> 5;          // 0..7
    const int bcol4 = (tid & 31) * 4;    // 0..124

    const int ty = tid >> 4;             // 0..15
    const int tx = tid & 15;             // 0..15

    float acc[TM][TN];
    #pragma unroll
    for (int i = 0; i < TM; i++)
        #pragma unroll
        for (int j = 0; j < TN; j++) acc[i][j] = 0.0f;

    for (int k0 = 0; k0 < K; k0 += BK) {
        float4 av = *reinterpret_cast<const float4*>(A + (size_t)arow * K + k0 + acol4);
        As[acol4 + 0][arow] = av.x;
        As[acol4 + 1][arow] = av.y;
        As[acol4 + 2][arow] = av.z;
        As[acol4 + 3][arow] = av.w;
        *reinterpret_cast<float4*>(&Bs[brw][bcol4]) =
            *reinterpret_cast<const float4*>(B + (size_t)(k0 + brw) * N + bcol4);
        __syncthreads();

        #pragma unroll
        for (int k = 0; k < BK; k++) {
            float ra[TM], rb[TN];
            float4 a0 = *reinterpret_cast<float4*>(&As[k][ty * TM]);
            float4 a1 = *reinterpret_cast<float4*>(&As[k][ty * TM + 4]);
            ra[0]=a0.x; ra[1]=a0.y; ra[2]=a0.z; ra[3]=a0.w;
            ra[4]=a1.x; ra[5]=a1.y; ra[6]=a1.z; ra[7]=a1.w;
            float4 b0 = *reinterpret_cast<float4*>(&Bs[k][tx * TN]);
            float4 b1 = *reinterpret_cast<float4*>(&Bs[k][tx * TN + 4]);
            rb[0]=b0.x; rb[1]=b0.y; rb[2]=b0.z; rb[3]=b0.w;
            rb[4]=b1.x; rb[5]=b1.y; rb[6]=b1.z; rb[7]=b1.w;
            #pragma unroll
            for (int i = 0; i < TM; i++)
                #pragma unroll
                for (int j = 0; j < TN; j++)
                    acc[i][j] = fmaf(ra[i], rb[j], acc[i][j]);
        }
        __syncthreads();
    }

    const bool do_tanh = flags & 1;
    const bool do_acc  = flags & 2;
    #pragma unroll
    for (int i = 0; i < TM; i++) {
        int row = brow * BM + ty * TM + i;
        #pragma unroll
        for (int j = 0; j < TN; j++) {
            int col = bcol * BN + tx * TN + j;
            float v = acc[i][j];
            size_t idx = (size_t)row * N + col;
            if (do_acc)  v += C[idx];
            if (bias)    v += bias[col];
            if (do_tanh) v = tanhf(v);
            C[idx] = v;
        }
    }
}

// ---------------- f = exp(x @ fi_w), one warp per row ----------------
__global__ void rowdot_exp_kernel(const float* __restrict__ x,
                                  const float* __restrict__ w,
                                  float* __restrict__ out, int K)
{
    int row  = blockIdx.x * 8 + (threadIdx.x >> 5);
    int lane = threadIdx.x & 31;
    const float* xr = x + (size_t)row * K;
    float s = 0.0f;
    for (int k = lane; k < K; k += 32) s += xr[k] * w[k];
    #pragma unroll
    for (int o = 16; o > 0; o >>= 1) s += __shfl_xor_sync(0xffffffffu, s, o);
    if (lane == 0) out[row] = expf(s);
}

// ---------------- s[m] = dot(u[m,:], tc[m,:]) ----------------
__global__ void rowdot_mul_kernel(const float* __restrict__ u,
                                  const float* __restrict__ tc,
                                  float* __restrict__ out, int K)
{
    int row  = blockIdx.x * 8 + (threadIdx.x >> 5);
    int lane = threadIdx.x & 31;
    const float* ur = u  + (size_t)row * K;
    const float* tr = tc + (size_t)row * K;
    float s = 0.0f;
    for (int k = lane; k < K; k += 32) s += ur[k] * tr[k];
    #pragma unroll
    for (int o = 16; o > 0; o >>= 1) s += __shfl_xor_sync(0xffffffffu, s, o);
    if (lane == 0) out[row] = s;
}

// ---------------- per-batch: smax, a=exp(s-smax), S=sum a, Q=sum a*f ----------
__global__ void stats_kernel(const float* __restrict__ s,
                             const float* __restrict__ f,
                             float* __restrict__ a,
                             float* __restrict__ Sb, float* __restrict__ Qb)
{
    __shared__ float red[256];
    int b = blockIdx.x;
    int t = threadIdx.x;
    const float* sb = s + b * Nn;
    const float* fb = f + b * Nn;
    float* ab = a + b * Nn;

    float mx = -1e30f;
    for (int i = t; i < Nn; i += 256) mx = fmaxf(mx, sb[i]);
    red[t] = mx; __syncthreads();
    for (int off = 128; off > 0; off >>= 1) {
        if (t < off) red[t] = fmaxf(red[t], red[t + off]);
        __syncthreads();
    }
    mx = red[0]; __syncthreads();

    float ls = 0.0f, lq = 0.0f;
    for (int i = t; i < Nn; i += 256) {
        float av = expf(sb[i] - mx);
        ab[i] = av;
        ls += av;
        lq += av * fb[i];
    }
    red[t] = ls; __syncthreads();
    for (int off = 128; off > 0; off >>= 1) {
        if (t < off) red[t] += red[t + off];
        __syncthreads();
    }
    float S = red[0]; __syncthreads();
    red[t] = lq; __syncthreads();
    for (int off = 128; off > 0; off >>= 1) {
        if (t < off) red[t] += red[t + off];
        __syncthreads();
    }
    if (t == 0) { Sb[b] = S; Qb[b] = red[0]; }
}

// ---------------- zero p/q ----------------
__global__ void zero_kernel(float* __restrict__ p, int n)
{
    int i = blockIdx.x * blockDim.x + threadIdx.x;
    if (i < n) p[i] = 0.0f;
}

// ---------------- p[b,e]=sum_n a*Y, q[b,e]=sum_n a*f*Y ----------------
__global__ void pq_kernel(const float* __restrict__ Y,
                          const float* __restrict__ a,
                          const float* __restrict__ f,
                          float* __restrict__ p, float* __restrict__ q)
{
    int b = blockIdx.x;
    int chunk = blockIdx.y;            // 8 chunks of 128 rows
    int e = threadIdx.x;               // 256 columns
    const float* Yb = Y + ((size_t)b * Nn + chunk * 128) * Hh;
    const float* ab = a + b * Nn + chunk * 128;
    const float* fb = f + b * Nn + chunk * 128;
    float lp = 0.0f, lq = 0.0f;
    for (int n = 0; n < 128; n++) {
        float av = ab[n];
        float y  = Yb[(size_t)n * Hh + e];
        lp += av * y;
        lq += av * fb[n] * y;
    }
    atomicAdd(&p[b * Hh + e], lp);
    atomicAdd(&q[b * Hh + e], lq);
}

// ---------------- GCN epilogue: g = relu((adjY + Y + 2b)/denom) --------------
// adjY[m] = ((1 - a_m f_m/Q) p + (a_m/Q) q - a_m Y[m]) / S ;  denom = 2 - a_m f_m/Q
__global__ void gcn_epilogue_kernel(const float* __restrict__ Y,
                                    const float* __restrict__ p,
                                    const float* __restrict__ q,
                                    const float* __restrict__ a,
                                    const float* __restrict__ f,
                                    const float* __restrict__ Sb,
                                    const float* __restrict__ Qb,
                                    const float* __restrict__ bias,
                                    float* __restrict__ G)
{
    int idx = blockIdx.x * blockDim.x + threadIdx.x;   // over Mrows*Hh
    int e = idx & (Hh - 1);
    int m = idx >> 8;
    int b = m >> 10;
    float am = a[m], fm = f[m];
    float S = Sb[b], Q = Qb[b];
    float t = am * fm / Q;
    float y = Y[idx];
    float adjy = ((1.0f - t) * p[b * Hh + e] + (am / Q) * q[b * Hh + e] - am * y) / S;
    float v = (adjy + y + 2.0f * bias[e]) / (2.0f - t);
    G[idx] = fmaxf(v, 0.0f);
}

// ---------------- h = concat(g1,g2) + x ----------------
__global__ void build_h_kernel(const float* __restrict__ x,
                               const float* __restrict__ g1,
                               const float* __restrict__ g2,
                               float* __restrict__ h)
{
    int idx = blockIdx.x * blockDim.x + threadIdx.x;   // over Mrows*Dd
    int e = idx & (Dd - 1);
    int m = idx >> 9;
    float g = (e < Hh) ? g1[(size_t)m * Hh + e] : g2[(size_t)m * Hh + (e - Hh)];
    h[idx] = g + x[idx];
}

// ---------------- launcher ----------------
extern "C" void kernel_launch(void* const* d_in, const int* in_sizes, int n_in,
                              void* d_out, int out_size)
{
    const float* x      = (const float*)d_in[0];
    const float* tp_w   = (const float*)d_in[1];
    const float* tp_b   = (const float*)d_in[2];
    const float* tc_w   = (const float*)d_in[3];
    const float* tc_b   = (const float*)d_in[4];
    const float* fi_w   = (const float*)d_in[5];
    const float* bil_w  = (const float*)d_in[6];
    const float* gcn_w0 = (const float*)d_in[7];
    const float* gcn_b0 = (const float*)d_in[8];
    const float* gcn_w1 = (const float*)d_in[9];
    const float* gcn_b1 = (const float*)d_in[10];
    const float* out_w  = (const float*)d_in[11];
    const float* out_b  = (const float*)d_in[12];
    float* out = (float*)d_out;

    float *tp, *tc, *u, *h, *y, *g1, *g2, *fv, *sv, *av, *Sb, *Qb, *pq;
    cudaGetSymbolAddress((void**)&tp, g_tp);
    cudaGetSymbolAddress((void**)&tc, g_tc);
    cudaGetSymbolAddress((void**)&u,  g_u);
    cudaGetSymbolAddress((void**)&h,  g_h);
    cudaGetSymbolAddress((void**)&y,  g_y);
    cudaGetSymbolAddress((void**)&g1, g_g1);
    cudaGetSymbolAddress((void**)&g2, g_g2);
    cudaGetSymbolAddress((void**)&fv, g_f);
    cudaGetSymbolAddress((void**)&sv, g_sv);
    cudaGetSymbolAddress((void**)&av, g_a);
    cudaGetSymbolAddress((void**)&Sb, g_S);
    cudaGetSymbolAddress((void**)&Qb, g_Q);
    cudaGetSymbolAddress((void**)&pq, g_pq);
    float* pv = pq;
    float* qv = pq + Bb * Hh;

    dim3 gD(Dd / 128, Mrows / 128);   // N=512
    dim3 gH(Hh / 128, Mrows / 128);   // N=256

    // 1) tp = tanh(x@tp_w + tp_b), tc = tanh(x@tc_w + tc_b)
    sgemm_kernel<<<gD, 256>>>(x, tp_w, tp_b, tp, Mrows, Dd, Dd, 1);
    sgemm_kernel<<<gD, 256>>>(x, tc_w, tc_b, tc, Mrows, Dd, Dd, 1);

    // 2) f = exp(x @ fi_w)
    rowdot_exp_kernel<<<Mrows / 8, 256>>>(x, fi_w, fv, Dd);

    // 3) u = tp @ bil_w ; s = rowdot(u, tc)
    sgemm_kernel<<<gD, 256>>>(tp, bil_w, nullptr, u, Mrows, Dd, Dd, 0);
    rowdot_mul_kernel<<<Mrows / 8, 256>>>(u, tc, sv, Dd);

    // 4) per-batch stats: a = exp(s - smax), S, Q
    stats_kernel<<<Bb, 256>>>(sv, fv, av, Sb, Qb);

    // 5) GCN layer 1: Y1 = x @ gcn_w0 ; p,q ; g1
    sgemm_kernel<<<gH, 256>>>(x, gcn_w0, nullptr, y, Mrows, Hh, Dd, 0);
    zero_kernel<<<(2 * Bb * Hh + 255) / 256, 256>>>(pq, 2 * Bb * Hh);
    pq_kernel<<<dim3(Bb, 8), 256>>>(y, av, fv, pv, qv);
    gcn_epilogue_kernel<<<(Mrows * Hh) / 256, 256>>>(y, pv, qv, av, fv, Sb, Qb, gcn_b0, g1);

    // 6) GCN layer 2: Y2 = x @ W1[:512] + g1 @ W1[512:] ; p,q ; g2
    sgemm_kernel<<<gH, 256>>>(x, gcn_w1, nullptr, y, Mrows, Hh, Dd, 0);
    sgemm_kernel<<<gH, 256>>>(g1, gcn_w1 + (size_t)Dd * Hh, nullptr, y, Mrows, Hh, Hh, 2);
    zero_kernel<<<(2 * Bb * Hh + 255) / 256, 256>>>(pq, 2 * Bb * Hh);
    pq_kernel<<<dim3(Bb, 8), 256>>>(y, av, fv, pv, qv);
    gcn_epilogue_kernel<<<(Mrows * Hh) / 256, 256>>>(y, pv, qv, av, fv, Sb, Qb, gcn_b1, g2);

    // 7) h = concat(g1,g2) + x ; out = h @ out_w + out_b
    build_h_kernel<<<(Mrows * Dd) / 256, 256>>>(x, g1, g2, h);
    sgemm_kernel<<<gD, 256>>>(h, out_w, out_b, out, Mrows, Dd, Dd, 0);
}

// round 8
// speedup vs baseline: 1.9890x; 1.9890x over previous
#include <cuda_runtime.h>
#include <cuda_bf16.h>
#include <math.h>
#include <stdint.h>

#define Bb   16
#define Nn   1024
#define Dd   512
#define Hh   256
#define Mrows (Bb*Nn)   // 16384

// ---------------- scratch (static device globals; no allocation) ----------------
__device__ float g_tp[Mrows*Dd];
__device__ float g_tc[Mrows*Dd];
__device__ float g_u [Mrows*Dd];
__device__ float g_h [Mrows*Dd];
__device__ float g_y [Mrows*Hh];
__device__ float g_g1[Mrows*Hh];
__device__ float g_g2[Mrows*Hh];
__device__ float g_f [Mrows];
__device__ float g_sv[Mrows];
__device__ float g_a [Mrows];
__device__ float g_S [Bb];
__device__ float g_Q [Bb];
__device__ float g_pq[2*Bb*Hh];

// split-bf16 weights, transposed to [N, K] row-major
#define WTOT 1376256
__device__ __nv_bfloat16 g_whi[WTOT];
__device__ __nv_bfloat16 g_wlo[WTOT];
#define OTP   0
#define OTC   262144
#define OBIL  524288
#define OW0   786432        // 256 x 512
#define OW1   917504        // 256 x 768
#define OOUT  1114112       // 512 x 512

// ================= helpers =================
__device__ __forceinline__ uint32_t smem_to_u32(const void* p) {
    uint32_t a;
    asm("{ .reg .u64 t; cvta.to.shared.u64 t, %1; cvt.u32.u64 %0, t; }" : "=r"(a) : "l"(p));
    return a;
}
__device__ __forceinline__ uint32_t pack_bf16(float x, float y) {
    __nv_bfloat16 a = __float2bfloat16(x), b = __float2bfloat16(y);
    return (uint32_t)__bfloat16_as_ushort(a) | ((uint32_t)__bfloat16_as_ushort(b) << 16);
}
__device__ __forceinline__ float bf_hi(float x) {
    return __bfloat162float(__float2bfloat16(x));
}

#define LDSM4(r, addr) \
    asm volatile("ldmatrix.sync.aligned.m8n8.x4.shared.b16 {%0,%1,%2,%3}, [%4];" \
        : "=r"((r)[0]), "=r"((r)[1]), "=r"((r)[2]), "=r"((r)[3]) : "r"(addr))

#define MMA_BF16(c, a, b0, b1) \
    asm volatile("mma.sync.aligned.m16n8k16.row.col.f32.bf16.bf16.f32 " \
        "{%0,%1,%2,%3}, {%4,%5,%6,%7}, {%8,%9}, {%0,%1,%2,%3};" \
        : "+f"((c)[0]), "+f"((c)[1]), "+f"((c)[2]), "+f"((c)[3]) \
        : "r"((a)[0]), "r"((a)[1]), "r"((a)[2]), "r"((a)[3]), "r"(b0), "r"(b1))

#define STS128(addr, v) \
    asm volatile("st.shared.v4.b32 [%0], {%1,%2,%3,%4};" \
        :: "r"(addr), "r"((v).x), "r"((v).y), "r"((v).z), "r"((v).w))

// ================= weight prep: W[K,N] fp32 -> hi/lo bf16 [N,K] =================
__global__ void prep_weights_kernel(const float* __restrict__ W,
                                    __nv_bfloat16* __restrict__ hi,
                                    __nv_bfloat16* __restrict__ lo,
                                    int K, int N)
{
    int idx = blockIdx.x * blockDim.x + threadIdx.x;
    if (idx >= K * N) return;
    int k = idx / N, n = idx % N;
    float v = W[idx];
    __nv_bfloat16 h = __float2bfloat16(v);
    float r = v - __bfloat162float(h);
    hi[(size_t)n * K + k] = h;
    lo[(size_t)n * K + k] = __float2bfloat16(r);
}

// ================= warp-MMA split-bf16 GEMM =================
// C[M,N] = epi(A[M,K] @ B^T), B pre-split bf16 [N, ldb] rows (K-major).
// flags: bit0 tanh, bit1 accumulate into C.  grid=(N/128, M/128), 256 thr.
// smem per stage: Ah|Al|Bh|Bl each 128 rows x 40 bf16 (80B) = 10240B; stage=40960B.
#define LDBF 40
#define AH_OFF 0
#define AL_OFF 10240
#define BH_OFF 20480
#define BL_OFF 30720
#define STG    40960
#define GEMM_SMEM_BYTES (2*STG)

__global__ __launch_bounds__(256) void gemm_mma_kernel(
    const float* __restrict__ A, int lda,
    const __nv_bfloat16* __restrict__ Bhi, const __nv_bfloat16* __restrict__ Blo,
    int ldb, int bk0,
    const float* __restrict__ bias,
    float* __restrict__ C, int ldc,
    int K, int flags)
{
    extern __shared__ __align__(16) char smem[];
    const uint32_t sbase = smem_to_u32(smem);

    const int tid  = threadIdx.x;
    const int lane = tid & 31;
    const int wid  = tid >> 5;
    const int wm   = wid & 3;          // 4 warps along M
    const int wn   = wid >> 2;         // 2 warps along N
    const int rowBase = blockIdx.y * 128;
    const int colBase = blockIdx.x * 128;
    const int KT = K >> 5;

    // ---- loader indices: thread t -> row t/2, col halves of 16
    const int lrow = tid >> 1;
    const int lcol = (tid & 1) * 16;
    const float* Ag          = A   + (size_t)(rowBase + lrow) * lda + lcol;
    const __nv_bfloat16* Bhg = Bhi + (size_t)(colBase + lrow) * ldb + bk0 + lcol;
    const __nv_bfloat16* Blg = Blo + (size_t)(colBase + lrow) * ldb + bk0 + lcol;
    const uint32_t sAr = sbase + (uint32_t)(lrow * LDBF + lcol) * 2;
    const uint32_t sBr = sAr + BH_OFF;

    float4 fa[4];
    uint4  pbh[2], pbl[2];

    // ---- ldmatrix addresses (within-stage offsets, bytes)
    // A: tile mi: lanes -> row = wm*32 + mi*16 + (lane&15), k-chunk = (lane>>4)*8
    uint32_t aoff[2];
    #pragma unroll
    for (int mi = 0; mi < 2; mi++) {
        int r = wm * 32 + mi * 16 + (lane & 15);
        aoff[mi] = (uint32_t)(r * LDBF + (lane >> 4) * 8) * 2;
    }
    // B: group g: tile = lane>>3; n = wn*64 + g*16 + (tile>>1)*8 + (lane&7); k-chunk=(tile&1)*8
    uint32_t boff[4];
    {
        int tile = lane >> 3;
        #pragma unroll
        for (int g = 0; g < 4; g++) {
            int n = wn * 64 + g * 16 + (tile >> 1) * 8 + (lane & 7);
            boff[g] = (uint32_t)(n * LDBF + (tile & 1) * 8) * 2 + BH_OFF;
        }
    }

    float acc[2][8][4];
    #pragma unroll
    for (int mi = 0; mi < 2; mi++)
        #pragma unroll
        for (int nf = 0; nf < 8; nf++)
            #pragma unroll
            for (int r = 0; r < 4; r++) acc[mi][nf][r] = 0.0f;

    // ---- gmem load of tile kt into regs
    auto g_load = [&](int kt) {
        const float* ap = Ag + kt * 32;
        #pragma unroll
        for (int i = 0; i < 4; i++)
            fa[i] = *reinterpret_cast<const float4*>(ap + i * 4);
        const __nv_bfloat16* bh = Bhg + kt * 32;
        const __nv_bfloat16* bl = Blg + kt * 32;
        pbh[0] = *reinterpret_cast<const uint4*>(bh);
        pbh[1] = *reinterpret_cast<const uint4*>(bh + 8);
        pbl[0] = *reinterpret_cast<const uint4*>(bl);
        pbl[1] = *reinterpret_cast<const uint4*>(bl + 8);
    };
    // ---- regs -> smem stage s (split A)
    auto s_store = [&](int s) {
        uint32_t so = (uint32_t)s * STG;
        uint4 H, L;
        #pragma unroll
        for (int half = 0; half < 2; half++) {
            float4 v0 = fa[half * 2], v1 = fa[half * 2 + 1];
            H.x = pack_bf16(v0.x, v0.y); H.y = pack_bf16(v0.z, v0.w);
            H.z = pack_bf16(v1.x, v1.y); H.w = pack_bf16(v1.z, v1.w);
            L.x = pack_bf16(v0.x - bf_hi(v0.x), v0.y - bf_hi(v0.y));
            L.y = pack_bf16(v0.z - bf_hi(v0.z), v0.w - bf_hi(v0.w));
            L.z = pack_bf16(v1.x - bf_hi(v1.x), v1.y - bf_hi(v1.y));
            L.w = pack_bf16(v1.z - bf_hi(v1.z), v1.w - bf_hi(v1.w));
            STS128(sAr + so + AH_OFF + half * 16, H);
            STS128(sAr + so + AL_OFF + half * 16, L);
        }
        STS128(sBr + so,                  pbh[0]);
        STS128(sBr + so + 16,             pbh[1]);
        STS128(sBr + so + (BL_OFF-BH_OFF),      pbl[0]);
        STS128(sBr + so + (BL_OFF-BH_OFF) + 16, pbl[1]);
    };
    // ---- compute on stage s
    auto compute = [&](int s) {
        uint32_t so = sbase + (uint32_t)s * STG;
        #pragma unroll
        for (int ks = 0; ks < 2; ks++) {
            uint32_t kb = (uint32_t)(ks * 16) * 2;
            uint32_t ah[2][4], al[2][4];
            #pragma unroll
            for (int mi = 0; mi < 2; mi++) {
                LDSM4(ah[mi], so + AH_OFF + aoff[mi] + kb);
                LDSM4(al[mi], so + AL_OFF + aoff[mi] + kb);
            }
            #pragma unroll
            for (int g = 0; g < 4; g++) {
                uint32_t bh[4], bl[4];
                LDSM4(bh, so + boff[g] + kb);
                LDSM4(bl, so + boff[g] + kb + (BL_OFF - BH_OFF));
                #pragma unroll
                for (int mi = 0; mi < 2; mi++) {
                    #pragma unroll
                    for (int sub = 0; sub < 2; sub++) {
                        float* c = acc[mi][g * 2 + sub];
                        MMA_BF16(c, ah[mi], bh[2*sub], bh[2*sub+1]);
                        MMA_BF16(c, ah[mi], bl[2*sub], bl[2*sub+1]);
                        MMA_BF16(c, al[mi], bh[2*sub], bh[2*sub+1]);
                    }
                }
            }
        }
    };

    // ---- pipeline
    g_load(0);
    s_store(0);
    __syncthreads();
    for (int kt = 0; kt < KT; kt++) {
        if (kt + 1 < KT) g_load(kt + 1);
        compute(kt & 1);
        if (kt + 1 < KT) s_store((kt + 1) & 1);
        __syncthreads();
    }

    // ---- epilogue
    const bool do_tanh = flags & 1, do_acc = flags & 2;
    #pragma unroll
    for (int mi = 0; mi < 2; mi++) {
        #pragma unroll
        for (int nf = 0; nf < 8; nf++) {
            int row = rowBase + wm * 32 + mi * 16 + (lane >> 2);
            int col = colBase + wn * 64 + nf * 8 + (lane & 3) * 2;
            float* c = acc[mi][nf];
            #pragma unroll
            for (int h = 0; h < 2; h++) {
                int r = row + h * 8;
                float vx = c[h * 2 + 0], vy = c[h * 2 + 1];
                float* Cp = C + (size_t)r * ldc + col;
                if (do_acc) { float2 o = *reinterpret_cast<const float2*>(Cp); vx += o.x; vy += o.y; }
                if (bias)   { vx += bias[col]; vy += bias[col + 1]; }
                if (do_tanh){ vx = tanhf(vx); vy = tanhf(vy); }
                float2 v; v.x = vx; v.y = vy;
                *reinterpret_cast<float2*>(Cp) = v;
            }
        }
    }
}

// ================= elementwise / reduction kernels =================
__global__ void rowdot_exp_kernel(const float* __restrict__ x,
                                  const float* __restrict__ w,
                                  float* __restrict__ out, int K)
{
    int row  = blockIdx.x * 8 + (threadIdx.x >> 5);
    int lane = threadIdx.x & 31;
    const float* xr = x + (size_t)row * K;
    float s = 0.0f;
    for (int k = lane; k < K; k += 32) s += xr[k] * w[k];
    #pragma unroll
    for (int o = 16; o > 0; o >>= 1) s += __shfl_xor_sync(0xffffffffu, s, o);
    if (lane == 0) out[row] = expf(s);
}

__global__ void rowdot_mul_kernel(const float* __restrict__ u,
                                  const float* __restrict__ tc,
                                  float* __restrict__ out, int K)
{
    int row  = blockIdx.x * 8 + (threadIdx.x >> 5);
    int lane = threadIdx.x & 31;
    const float* ur = u  + (size_t)row * K;
    const float* tr = tc + (size_t)row * K;
    float s = 0.0f;
    for (int k = lane; k < K; k += 32) s += ur[k] * tr[k];
    #pragma unroll
    for (int o = 16; o > 0; o >>= 1) s += __shfl_xor_sync(0xffffffffu, s, o);
    if (lane == 0) out[row] = s;
}

__global__ void stats_kernel(const float* __restrict__ s,
                             const float* __restrict__ f,
                             float* __restrict__ a,
                             float* __restrict__ Sb, float* __restrict__ Qb)
{
    __shared__ float red[256];
    int b = blockIdx.x;
    int t = threadIdx.x;
    const float* sb = s + b * Nn;
    const float* fb = f + b * Nn;
    float* ab = a + b * Nn;

    float mx = -1e30f;
    for (int i = t; i < Nn; i += 256) mx = fmaxf(mx, sb[i]);
    red[t] = mx; __syncthreads();
    for (int off = 128; off > 0; off >>= 1) {
        if (t < off) red[t] = fmaxf(red[t], red[t + off]);
        __syncthreads();
    }
    mx = red[0]; __syncthreads();

    float ls = 0.0f, lq = 0.0f;
    for (int i = t; i < Nn; i += 256) {
        float av = expf(sb[i] - mx);
        ab[i] = av;
        ls += av;
        lq += av * fb[i];
    }
    red[t] = ls; __syncthreads();
    for (int off = 128; off > 0; off >>= 1) {
        if (t < off) red[t] += red[t + off];
        __syncthreads();
    }
    float S = red[0]; __syncthreads();
    red[t] = lq; __syncthreads();
    for (int off = 128; off > 0; off >>= 1) {
        if (t < off) red[t] += red[t + off];
        __syncthreads();
    }
    if (t == 0) { Sb[b] = S; Qb[b] = red[0]; }
}

__global__ void zero_kernel(float* __restrict__ p, int n)
{
    int i = blockIdx.x * blockDim.x + threadIdx.x;
    if (i < n) p[i] = 0.0f;
}

__global__ void pq_kernel(const float* __restrict__ Y,
                          const float* __restrict__ a,
                          const float* __restrict__ f,
                          float* __restrict__ p, float* __restrict__ q)
{
    int b = blockIdx.x;
    int chunk = blockIdx.y;
    int e = threadIdx.x;
    const float* Yb = Y + ((size_t)b * Nn + chunk * 128) * Hh;
    const float* ab = a + b * Nn + chunk * 128;
    const float* fb = f + b * Nn + chunk * 128;
    float lp = 0.0f, lq = 0.0f;
    for (int n = 0; n < 128; n++) {
        float av = ab[n];
        float y  = Yb[(size_t)n * Hh + e];
        lp += av * y;
        lq += av * fb[n] * y;
    }
    atomicAdd(&p[b * Hh + e], lp);
    atomicAdd(&q[b * Hh + e], lq);
}

__global__ void gcn_epilogue_kernel(const float* __restrict__ Y,
                                    const float* __restrict__ p,
                                    const float* __restrict__ q,
                                    const float* __restrict__ a,
                                    const float* __restrict__ f,
                                    const float* __restrict__ Sb,
                                    const float* __restrict__ Qb,
                                    const float* __restrict__ bias,
                                    float* __restrict__ G)
{
    int idx = blockIdx.x * blockDim.x + threadIdx.x;
    int e = idx & (Hh - 1);
    int m = idx >> 8;
    int b = m >> 10;
    float am = a[m], fm = f[m];
    float S = Sb[b], Q = Qb[b];
    float t = am * fm / Q;
    float y = Y[idx];
    float adjy = ((1.0f - t) * p[b * Hh + e] + (am / Q) * q[b * Hh + e] - am * y) / S;
    float v = (adjy + y + 2.0f * bias[e]) / (2.0f - t);
    G[idx] = fmaxf(v, 0.0f);
}

__global__ void build_h_kernel(const float* __restrict__ x,
                               const float* __restrict__ g1,
                               const float* __restrict__ g2,
                               float* __restrict__ h)
{
    int idx = blockIdx.x * blockDim.x + threadIdx.x;
    int e = idx & (Dd - 1);
    int m = idx >> 9;
    float g = (e < Hh) ? g1[(size_t)m * Hh + e] : g2[(size_t)m * Hh + (e - Hh)];
    h[idx] = g + x[idx];
}

// ================= launcher =================
extern "C" void kernel_launch(void* const* d_in, const int* in_sizes, int n_in,
                              void* d_out, int out_size)
{
    const float* x      = (const float*)d_in[0];
    const float* tp_w   = (const float*)d_in[1];
    const float* tp_b   = (const float*)d_in[2];
    const float* tc_w   = (const float*)d_in[3];
    const float* tc_b   = (const float*)d_in[4];
    const float* fi_w   = (const float*)d_in[5];
    const float* bil_w  = (const float*)d_in[6];
    const float* gcn_w0 = (const float*)d_in[7];
    const float* gcn_b0 = (const float*)d_in[8];
    const float* gcn_w1 = (const float*)d_in[9];
    const float* gcn_b1 = (const float*)d_in[10];
    const float* out_w  = (const float*)d_in[11];
    const float* out_b  = (const float*)d_in[12];
    float* out = (float*)d_out;

    float *tp, *tc, *u, *h, *y, *g1, *g2, *fv, *sv, *av, *Sb, *Qb, *pq;
    __nv_bfloat16 *whi, *wlo;
    cudaGetSymbolAddress((void**)&tp, g_tp);
    cudaGetSymbolAddress((void**)&tc, g_tc);
    cudaGetSymbolAddress((void**)&u,  g_u);
    cudaGetSymbolAddress((void**)&h,  g_h);
    cudaGetSymbolAddress((void**)&y,  g_y);
    cudaGetSymbolAddress((void**)&g1, g_g1);
    cudaGetSymbolAddress((void**)&g2, g_g2);
    cudaGetSymbolAddress((void**)&fv, g_f);
    cudaGetSymbolAddress((void**)&sv, g_sv);
    cudaGetSymbolAddress((void**)&av, g_a);
    cudaGetSymbolAddress((void**)&Sb, g_S);
    cudaGetSymbolAddress((void**)&Qb, g_Q);
    cudaGetSymbolAddress((void**)&pq, g_pq);
    cudaGetSymbolAddress((void**)&whi, g_whi);
    cudaGetSymbolAddress((void**)&wlo, g_wlo);
    float* pv = pq;
    float* qv = pq + Bb * Hh;

    cudaFuncSetAttribute(gemm_mma_kernel, cudaFuncAttributeMaxDynamicSharedMemorySize, GEMM_SMEM_BYTES);

    // ---- weight prep (transpose + split-bf16) ----
    prep_weights_kernel<<<(512*512+255)/256, 256>>>(tp_w,   whi+OTP,  wlo+OTP,  512, 512);
    prep_weights_kernel<<<(512*512+255)/256, 256>>>(tc_w,   whi+OTC,  wlo+OTC,  512, 512);
    prep_weights_kernel<<<(512*512+255)/256, 256>>>(bil_w,  whi+OBIL, wlo+OBIL, 512, 512);
    prep_weights_kernel<<<(512*256+255)/256, 256>>>(gcn_w0, whi+OW0,  wlo+OW0,  512, 256);
    prep_weights_kernel<<<(768*256+255)/256, 256>>>(gcn_w1, whi+OW1,  wlo+OW1,  768, 256);
    prep_weights_kernel<<<(512*512+255)/256, 256>>>(out_w,  whi+OOUT, wlo+OOUT, 512, 512);

    dim3 gD(Dd / 128, Mrows / 128);   // N=512
    dim3 gH(Hh / 128, Mrows / 128);   // N=256

    // 1) tp = tanh(x@tp_w + tp_b), tc = tanh(x@tc_w + tc_b)
    gemm_mma_kernel<<<gD, 256, GEMM_SMEM_BYTES>>>(x, Dd, whi+OTP, wlo+OTP, 512, 0, tp_b, tp, Dd, 512, 1);
    gemm_mma_kernel<<<gD, 256, GEMM_SMEM_BYTES>>>(x, Dd, whi+OTC, wlo+OTC, 512, 0, tc_b, tc, Dd, 512, 1);

    // 2) f = exp(x @ fi_w)
    rowdot_exp_kernel<<<Mrows / 8, 256>>>(x, fi_w, fv, Dd);

    // 3) u = tp @ bil_w ; s = rowdot(u, tc)
    gemm_mma_kernel<<<gD, 256, GEMM_SMEM_BYTES>>>(tp, Dd, whi+OBIL, wlo+OBIL, 512, 0, nullptr, u, Dd, 512, 0);
    rowdot_mul_kernel<<<Mrows / 8, 256>>>(u, tc, sv, Dd);

    // 4) per-batch stats
    stats_kernel<<<Bb, 256>>>(sv, fv, av, Sb, Qb);

    // 5) GCN layer 1
    gemm_mma_kernel<<<gH, 256, GEMM_SMEM_BYTES>>>(x, Dd, whi+OW0, wlo+OW0, 512, 0, nullptr, y, Hh, 512, 0);
    zero_kernel<<<(2 * Bb * Hh + 255) / 256, 256>>>(pq, 2 * Bb * Hh);
    pq_kernel<<<dim3(Bb, 8), 256>>>(y, av, fv, pv, qv);
    gcn_epilogue_kernel<<<(Mrows * Hh) / 256, 256>>>(y, pv, qv, av, fv, Sb, Qb, gcn_b0, g1);

    // 6) GCN layer 2: Y2 = x @ W1[:512]  +  g1 @ W1[512:]
    gemm_mma_kernel<<<gH, 256, GEMM_SMEM_BYTES>>>(x,  Dd, whi+OW1, wlo+OW1, 768, 0,   nullptr, y, Hh, 512, 0);
    gemm_mma_kernel<<<gH, 256, GEMM_SMEM_BYTES>>>(g1, Hh, whi+OW1, wlo+OW1, 768, 512, nullptr, y, Hh, 256, 2);
    zero_kernel<<<(2 * Bb * Hh + 255) / 256, 256>>>(pq, 2 * Bb * Hh);
    pq_kernel<<<dim3(Bb, 8), 256>>>(y, av, fv, pv, qv);
    gcn_epilogue_kernel<<<(Mrows * Hh) / 256, 256>>>(y, pv, qv, av, fv, Sb, Qb, gcn_b1, g2);

    // 7) h = concat(g1,g2) + x ; out = h @ out_w + out_b
    build_h_kernel<<<(Mrows * Dd) / 256, 256>>>(x, g1, g2, h);
    gemm_mma_kernel<<<gD, 256, GEMM_SMEM_BYTES>>>(h, Dd, whi+OOUT, wlo+OOUT, 512, 0, out_b, out, Dd, 512, 0);
}

// round 10
// speedup vs baseline: 2.1066x; 1.0591x over previous
#include <cuda_runtime.h>
#include <cuda_bf16.h>
#include <math.h>
#include <stdint.h>

#define Bb   16
#define Nn   1024
#define Dd   512
#define Hh   256
#define Mrows (Bb*Nn)   // 16384

// ---------------- scratch (static device globals; no allocation) ----------------
__device__ float g_tptc[Mrows*1024];   // [tp | tc] fused output
__device__ float g_h [Mrows*Dd];       // concat(g1,g2)+x
__device__ float g_y [Mrows*Hh];
__device__ float g_g1[Mrows*Hh];
__device__ float g_g2[Mrows*Hh];
__device__ float g_f [Mrows];
__device__ float g_sv[Mrows];
__device__ float g_a [Mrows];
__device__ float g_S [Bb];
__device__ float g_Q [Bb];
__device__ float g_pq[2*Bb*Hh];
__device__ float g_bias[1024];         // concat(tp_b, tc_b)

// split-bf16 weights, transposed to [N, K] row-major
#define WTOT 1376256
__device__ __nv_bfloat16 g_whi[WTOT];
__device__ __nv_bfloat16 g_wlo[WTOT];
#define OTP   0
#define OTC   262144
#define OBIL  524288
#define OW0   786432        // 256 x 512
#define OW1   917504        // 256 x 768
#define OOUT  1114112       // 512 x 512

// ================= helpers =================
__device__ __forceinline__ uint32_t smem_to_u32(const void* p) {
    uint32_t a;
    asm("{ .reg .u64 t; cvta.to.shared.u64 t, %1; cvt.u32.u64 %0, t; }" : "=r"(a) : "l"(p));
    return a;
}
__device__ __forceinline__ uint32_t pack_bf16(float x, float y) {
    __nv_bfloat16 a = __float2bfloat16(x), b = __float2bfloat16(y);
    return (uint32_t)__bfloat16_as_ushort(a) | ((uint32_t)__bfloat16_as_ushort(b) << 16);
}
__device__ __forceinline__ float bf_hi(float x) {
    return __bfloat162float(__float2bfloat16(x));
}

#define LDSM4(r, addr) \
    asm volatile("ldmatrix.sync.aligned.m8n8.x4.shared.b16 {%0,%1,%2,%3}, [%4];" \
        : "=r"((r)[0]), "=r"((r)[1]), "=r"((r)[2]), "=r"((r)[3]) : "r"(addr))

#define MMA_BF16(c, a, b0, b1) \
    asm volatile("mma.sync.aligned.m16n8k16.row.col.f32.bf16.bf16.f32 " \
        "{%0,%1,%2,%3}, {%4,%5,%6,%7}, {%8,%9}, {%0,%1,%2,%3};" \
        : "+f"((c)[0]), "+f"((c)[1]), "+f"((c)[2]), "+f"((c)[3]) \
        : "r"((a)[0]), "r"((a)[1]), "r"((a)[2]), "r"((a)[3]), "r"(b0), "r"(b1))

#define STS128(addr, v) \
    asm volatile("st.shared.v4.b32 [%0], {%1,%2,%3,%4};" \
        :: "r"(addr), "r"((v).x), "r"((v).y), "r"((v).z), "r"((v).w))

#define CP_ASYNC16(dst, src) \
    asm volatile("cp.async.cg.shared.global [%0], [%1], 16;" :: "r"(dst), "l"(src))
#define CP_COMMIT() asm volatile("cp.async.commit_group;" ::: "memory")
#define CP_WAIT0()  asm volatile("cp.async.wait_group 0;" ::: "memory")

// ================= merged weight prep =================
// all 6 weights: W[K,N] fp32 -> hi/lo bf16 [N,K]; plus bias concat
__device__ __forceinline__ void split_one(const float* __restrict__ W,
                                          __nv_bfloat16* __restrict__ hi,
                                          __nv_bfloat16* __restrict__ lo,
                                          int local, int K, int N)
{
    int k = local / N, n = local % N;
    float v = W[local];
    __nv_bfloat16 h = __float2bfloat16(v);
    hi[(size_t)n * K + k] = h;
    lo[(size_t)n * K + k] = __float2bfloat16(v - __bfloat162float(h));
}

__global__ void prep_all_kernel(const float* __restrict__ tp_w, const float* __restrict__ tc_w,
                                const float* __restrict__ bil_w, const float* __restrict__ w0,
                                const float* __restrict__ w1, const float* __restrict__ ow,
                                const float* __restrict__ tp_b, const float* __restrict__ tc_b,
                                __nv_bfloat16* __restrict__ hi, __nv_bfloat16* __restrict__ lo,
                                float* __restrict__ bias)
{
    int idx = blockIdx.x * blockDim.x + threadIdx.x;
    if (idx < 262144)            split_one(tp_w,  hi+OTP,  lo+OTP,  idx,           512, 512);
    else if (idx < 524288)       split_one(tc_w,  hi+OTC,  lo+OTC,  idx - 262144,  512, 512);
    else if (idx < 786432)       split_one(bil_w, hi+OBIL, lo+OBIL, idx - 524288,  512, 512);
    else if (idx < 917504)       split_one(w0,    hi+OW0,  lo+OW0,  idx - 786432,  512, 256);
    else if (idx < 1114112)      split_one(w1,    hi+OW1,  lo+OW1,  idx - 917504,  768, 256);
    else if (idx < 1376256)      split_one(ow,    hi+OOUT, lo+OOUT, idx - 1114112, 512, 512);
    else if (idx < 1376256+512)  bias[idx - 1376256]       = tp_b[idx - 1376256];
    else if (idx < 1376256+1024) bias[idx - 1376256]       = tc_b[idx - 1376256 - 512];
}

// ================= warp-MMA split-bf16 GEMM =================
// C[M,N] = epi(A[M,K] @ B^T), B pre-split bf16 [N, ldb] rows (K-major).
// flags: bit0 tanh, bit1 accumulate, bit2 dot-epilogue (s += sum_col C*dotB; no C write)
#define LDBF 40
#define AH_OFF 0
#define AL_OFF 10240
#define BH_OFF 20480
#define BL_OFF 30720
#define STG    40960
#define GEMM_SMEM_BYTES (2*STG)

__global__ __launch_bounds__(256) void gemm_mma_kernel(
    const float* __restrict__ A, int lda,
    const __nv_bfloat16* __restrict__ Bhi, const __nv_bfloat16* __restrict__ Blo,
    int ldb, int bk0,
    const float* __restrict__ bias,
    float* __restrict__ C, int ldc,
    int K, int flags,
    const float* __restrict__ dotB, float* __restrict__ dotOut)
{
    extern __shared__ __align__(16) char smem[];
    const uint32_t sbase = smem_to_u32(smem);

    const int tid  = threadIdx.x;
    const int lane = tid & 31;
    const int wid  = tid >> 5;
    const int wm   = wid & 3;          // 4 warps along M
    const int wn   = wid >> 2;         // 2 warps along N
    const int rowBase = blockIdx.y * 128;
    const int colBase = blockIdx.x * 128;
    const int KT = K >> 5;

    const int lrow = tid >> 1;
    const int lcol = (tid & 1) * 16;
    const float* Ag          = A   + (size_t)(rowBase + lrow) * lda + lcol;
    const __nv_bfloat16* Bhg = Bhi + (size_t)(colBase + lrow) * ldb + bk0 + lcol;
    const __nv_bfloat16* Blg = Blo + (size_t)(colBase + lrow) * ldb + bk0 + lcol;
    const uint32_t sAr = sbase + (uint32_t)(lrow * LDBF + lcol) * 2;
    const uint32_t sBr = sAr + BH_OFF;

    float4 fa[4];

    uint32_t aoff[2];
    #pragma unroll
    for (int mi = 0; mi < 2; mi++) {
        int r = wm * 32 + mi * 16 + (lane & 15);
        aoff[mi] = (uint32_t)(r * LDBF + (lane >> 4) * 8) * 2;
    }
    uint32_t boff[4];
    {
        int tile = lane >> 3;
        #pragma unroll
        for (int g = 0; g < 4; g++) {
            int n = wn * 64 + g * 16 + (tile >> 1) * 8 + (lane & 7);
            boff[g] = (uint32_t)(n * LDBF + (tile & 1) * 8) * 2 + BH_OFF;
        }
    }

    float acc[2][8][4];
    #pragma unroll
    for (int mi = 0; mi < 2; mi++)
        #pragma unroll
        for (int nf = 0; nf < 8; nf++)
            #pragma unroll
            for (int r = 0; r < 4; r++) acc[mi][nf][r] = 0.0f;

    auto g_loadA = [&](int kt) {
        const float* ap = Ag + kt * 32;
        #pragma unroll
        for (int i = 0; i < 4; i++)
            fa[i] = *reinterpret_cast<const float4*>(ap + i * 4);
    };
    auto cp_B = [&](int kt, int s) {
        uint32_t so = (uint32_t)s * STG;
        const __nv_bfloat16* bh = Bhg + kt * 32;
        const __nv_bfloat16* bl = Blg + kt * 32;
        uint32_t d = sBr + so;
        CP_ASYNC16(d,                         bh);
        CP_ASYNC16(d + 16,                    bh + 8);
        CP_ASYNC16(d + (BL_OFF-BH_OFF),       bl);
        CP_ASYNC16(d + (BL_OFF-BH_OFF) + 16,  bl + 8);
        CP_COMMIT();
    };
    auto s_storeA = [&](int s) {
        uint32_t so = (uint32_t)s * STG;
        uint4 H, L;
        #pragma unroll
        for (int half = 0; half < 2; half++) {
            float4 v0 = fa[half * 2], v1 = fa[half * 2 + 1];
            H.x = pack_bf16(v0.x, v0.y); H.y = pack_bf16(v0.z, v0.w);
            H.z = pack_bf16(v1.x, v1.y); H.w = pack_bf16(v1.z, v1.w);
            L.x = pack_bf16(v0.x - bf_hi(v0.x), v0.y - bf_hi(v0.y));
            L.y = pack_bf16(v0.z - bf_hi(v0.z), v0.w - bf_hi(v0.w));
            L.z = pack_bf16(v1.x - bf_hi(v1.x), v1.y - bf_hi(v1.y));
            L.w = pack_bf16(v1.z - bf_hi(v1.z), v1.w - bf_hi(v1.w));
            STS128(sAr + so + AH_OFF + half * 16, H);
            STS128(sAr + so + AL_OFF + half * 16, L);
        }
    };
    auto compute = [&](int s) {
        uint32_t so = sbase + (uint32_t)s * STG;
        #pragma unroll
        for (int ks = 0; ks < 2; ks++) {
            uint32_t kb = (uint32_t)(ks * 16) * 2;
            uint32_t ah[2][4], al[2][4];
            #pragma unroll
            for (int mi = 0; mi < 2; mi++) {
                LDSM4(ah[mi], so + AH_OFF + aoff[mi] + kb);
                LDSM4(al[mi], so + AL_OFF + aoff[mi] + kb);
            }
            #pragma unroll
            for (int g = 0; g < 4; g++) {
                uint32_t bh[4], bl[4];
                LDSM4(bh, so + boff[g] + kb);
                LDSM4(bl, so + boff[g] + kb + (BL_OFF - BH_OFF));
                #pragma unroll
                for (int mi = 0; mi < 2; mi++) {
                    #pragma unroll
                    for (int sub = 0; sub < 2; sub++) {
                        float* c = acc[mi][g * 2 + sub];
                        MMA_BF16(c, ah[mi], bh[2*sub], bh[2*sub+1]);
                        MMA_BF16(c, ah[mi], bl[2*sub], bl[2*sub+1]);
                        MMA_BF16(c, al[mi], bh[2*sub], bh[2*sub+1]);
                    }
                }
            }
        }
    };

    // ---- pipeline: cp.async B overlaps compute; A staged via regs
    g_loadA(0);
    cp_B(0, 0);
    s_storeA(0);
    CP_WAIT0();
    __syncthreads();
    for (int kt = 0; kt < KT; kt++) {
        if (kt + 1 < KT) { g_loadA(kt + 1); cp_B(kt + 1, (kt + 1) & 1); }
        compute(kt & 1);
        if (kt + 1 < KT) s_storeA((kt + 1) & 1);
        CP_WAIT0();
        __syncthreads();
    }

    // ---- epilogues
    if (flags & 4) {
        // dot epilogue: dotOut[row] += sum_cols acc * dotB[row, col] (ldc = dotB leading dim)
        #pragma unroll
        for (int mi = 0; mi < 2; mi++) {
            #pragma unroll
            for (int h = 0; h < 2; h++) {
                int row = rowBase + wm * 32 + mi * 16 + (lane >> 2) + h * 8;
                const float* tb = dotB + (size_t)row * ldc + colBase + wn * 64;
                float p = 0.0f;
                #pragma unroll
                for (int nf = 0; nf < 8; nf++) {
                    int c = nf * 8 + (lane & 3) * 2;
                    float2 t = *reinterpret_cast<const float2*>(tb + c);
                    p += acc[mi][nf][h * 2 + 0] * t.x + acc[mi][nf][h * 2 + 1] * t.y;
                }
                p += __shfl_xor_sync(0xffffffffu, p, 1);
                p += __shfl_xor_sync(0xffffffffu, p, 2);
                if ((lane & 3) == 0) atomicAdd(dotOut + row, p);
            }
        }
        return;
    }
    const bool do_tanh = flags & 1, do_acc = flags & 2;
    #pragma unroll
    for (int mi = 0; mi < 2; mi++) {
        #pragma unroll
        for (int nf = 0; nf < 8; nf++) {
            int row = rowBase + wm * 32 + mi * 16 + (lane >> 2);
            int col = colBase + wn * 64 + nf * 8 + (lane & 3) * 2;
            float* c = acc[mi][nf];
            #pragma unroll
            for (int h = 0; h < 2; h++) {
                int r = row + h * 8;
                float vx = c[h * 2 + 0], vy = c[h * 2 + 1];
                float* Cp = C + (size_t)r * ldc + col;
                if (do_acc) { float2 o = *reinterpret_cast<const float2*>(Cp); vx += o.x; vy += o.y; }
                if (bias)   { vx += bias[col]; vy += bias[col + 1]; }
                if (do_tanh){ vx = tanhf(vx); vy = tanhf(vy); }
                float2 v; v.x = vx; v.y = vy;
                *reinterpret_cast<float2*>(Cp) = v;
            }
        }
    }
}

// ================= elementwise / reduction kernels =================
// f = exp(x @ fi_w); also zero sv for the bil dot-epilogue atomics
__global__ void rowdot_exp_kernel(const float* __restrict__ x,
                                  const float* __restrict__ w,
                                  float* __restrict__ out,
                                  float* __restrict__ svz, int K)
{
    int row  = blockIdx.x * 8 + (threadIdx.x >> 5);
    int lane = threadIdx.x & 31;
    const float* xr = x + (size_t)row * K;
    float s = 0.0f;
    for (int k = lane; k < K; k += 32) s += xr[k] * w[k];
    #pragma unroll
    for (int o = 16; o > 0; o >>= 1) s += __shfl_xor_sync(0xffffffffu, s, o);
    if (lane == 0) { out[row] = expf(s); svz[row] = 0.0f; }
}

__global__ void stats_kernel(const float* __restrict__ s,
                             const float* __restrict__ f,
                             float* __restrict__ a,
                             float* __restrict__ Sb, float* __restrict__ Qb)
{
    __shared__ float red[256];
    int b = blockIdx.x;
    int t = threadIdx.x;
    const float* sb = s + b * Nn;
    const float* fb = f + b * Nn;
    float* ab = a + b * Nn;

    float mx = -1e30f;
    for (int i = t; i < Nn; i += 256) mx = fmaxf(mx, sb[i]);
    red[t] = mx; __syncthreads();
    for (int off = 128; off > 0; off >>= 1) {
        if (t < off) red[t] = fmaxf(red[t], red[t + off]);
        __syncthreads();
    }
    mx = red[0]; __syncthreads();

    float ls = 0.0f, lq = 0.0f;
    for (int i = t; i < Nn; i += 256) {
        float av = expf(sb[i] - mx);
        ab[i] = av;
        ls += av;
        lq += av * fb[i];
    }
    red[t] = ls; __syncthreads();
    for (int off = 128; off > 0; off >>= 1) {
        if (t < off) red[t] += red[t + off];
        __syncthreads();
    }
    float S = red[0]; __syncthreads();
    red[t] = lq; __syncthreads();
    for (int off = 128; off > 0; off >>= 1) {
        if (t < off) red[t] += red[t + off];
        __syncthreads();
    }
    if (t == 0) { Sb[b] = S; Qb[b] = red[0]; }
}

__global__ void zero_kernel(float* __restrict__ p, int n)
{
    int i = blockIdx.x * blockDim.x + threadIdx.x;
    if (i < n) p[i] = 0.0f;
}

__global__ void pq_kernel(const float* __restrict__ Y,
                          const float* __restrict__ a,
                          const float* __restrict__ f,
                          float* __restrict__ p, float* __restrict__ q)
{
    int b = blockIdx.x;
    int chunk = blockIdx.y;
    int e = threadIdx.x;
    const float* Yb = Y + ((size_t)b * Nn + chunk * 128) * Hh;
    const float* ab = a + b * Nn + chunk * 128;
    const float* fb = f + b * Nn + chunk * 128;
    float lp = 0.0f, lq = 0.0f;
    for (int n = 0; n < 128; n++) {
        float av = ab[n];
        float y  = Yb[(size_t)n * Hh + e];
        lp += av * y;
        lq += av * fb[n] * y;
    }
    atomicAdd(&p[b * Hh + e], lp);
    atomicAdd(&q[b * Hh + e], lq);
}

// GCN epilogue; also writes its half of h = g + x (fuses build_h)
__global__ void gcn_epilogue_kernel(const float* __restrict__ Y,
                                    const float* __restrict__ p,
                                    const float* __restrict__ q,
                                    const float* __restrict__ a,
                                    const float* __restrict__ f,
                                    const float* __restrict__ Sb,
                                    const float* __restrict__ Qb,
                                    const float* __restrict__ bias,
                                    float* __restrict__ G,
                                    const float* __restrict__ x,
                                    float* __restrict__ h, int colOff)
{
    int idx = blockIdx.x * blockDim.x + threadIdx.x;
    int e = idx & (Hh - 1);
    int m = idx >> 8;
    int b = m >> 10;
    float am = a[m], fm = f[m];
    float S = Sb[b], Q = Qb[b];
    float t = am * fm / Q;
    float y = Y[idx];
    float adjy = ((1.0f - t) * p[b * Hh + e] + (am / Q) * q[b * Hh + e] - am * y) / S;
    float v = (adjy + y + 2.0f * bias[e]) / (2.0f - t);
    float g = fmaxf(v, 0.0f);
    G[idx] = g;
    size_t hx = (size_t)m * Dd + colOff + e;
    h[hx] = g + x[hx];
}

// ================= launcher =================
extern "C" void kernel_launch(void* const* d_in, const int* in_sizes, int n_in,
                              void* d_out, int out_size)
{
    const float* x      = (const float*)d_in[0];
    const float* tp_w   = (const float*)d_in[1];
    const float* tp_b   = (const float*)d_in[2];
    const float* tc_w   = (const float*)d_in[3];
    const float* tc_b   = (const float*)d_in[4];
    const float* fi_w   = (const float*)d_in[5];
    const float* bil_w  = (const float*)d_in[6];
    const float* gcn_w0 = (const float*)d_in[7];
    const float* gcn_b0 = (const float*)d_in[8];
    const float* gcn_w1 = (const float*)d_in[9];
    const float* gcn_b1 = (const float*)d_in[10];
    const float* out_w  = (const float*)d_in[11];
    const float* out_b  = (const float*)d_in[12];
    float* out = (float*)d_out;

    float *tptc, *h, *y, *g1, *g2, *fv, *sv, *av, *Sb, *Qb, *pq, *cbias;
    __nv_bfloat16 *whi, *wlo;
    cudaGetSymbolAddress((void**)&tptc, g_tptc);
    cudaGetSymbolAddress((void**)&h,  g_h);
    cudaGetSymbolAddress((void**)&y,  g_y);
    cudaGetSymbolAddress((void**)&g1, g_g1);
    cudaGetSymbolAddress((void**)&g2, g_g2);
    cudaGetSymbolAddress((void**)&fv, g_f);
    cudaGetSymbolAddress((void**)&sv, g_sv);
    cudaGetSymbolAddress((void**)&av, g_a);
    cudaGetSymbolAddress((void**)&Sb, g_S);
    cudaGetSymbolAddress((void**)&Qb, g_Q);
    cudaGetSymbolAddress((void**)&pq, g_pq);
    cudaGetSymbolAddress((void**)&cbias, g_bias);
    cudaGetSymbolAddress((void**)&whi, g_whi);
    cudaGetSymbolAddress((void**)&wlo, g_wlo);
    float* pv = pq;
    float* qv = pq + Bb * Hh;

    cudaFuncSetAttribute(gemm_mma_kernel, cudaFuncAttributeMaxDynamicSharedMemorySize, GEMM_SMEM_BYTES);

    // 0) merged weight prep (6 splits + bias concat) — one launch
    prep_all_kernel<<<(1376256 + 1024 + 255) / 256, 256>>>(
        tp_w, tc_w, bil_w, gcn_w0, gcn_w1, out_w, tp_b, tc_b, whi, wlo, cbias);

    dim3 gTT(1024 / 128, Mrows / 128);  // fused tp|tc: N=1024
    dim3 gD(Dd / 128, Mrows / 128);     // N=512
    dim3 gH(Hh / 128, Mrows / 128);     // N=256

    // 1) [tp | tc] = tanh(x @ [tp_w | tc_w] + [tp_b | tc_b])   (one fused GEMM)
    gemm_mma_kernel<<<gTT, 256, GEMM_SMEM_BYTES>>>(x, Dd, whi+OTP, wlo+OTP, 512, 0,
                                                   cbias, tptc, 1024, 512, 1, nullptr, nullptr);

    // 2) f = exp(x @ fi_w); zero sv
    rowdot_exp_kernel<<<Mrows / 8, 256>>>(x, fi_w, fv, sv, Dd);

    // 3) s = rowdot(tp @ bil_w, tc) — dot fused into GEMM epilogue, u never materialized
    gemm_mma_kernel<<<gD, 256, GEMM_SMEM_BYTES>>>(tptc, 1024, whi+OBIL, wlo+OBIL, 512, 0,
                                                  nullptr, nullptr, 1024, 512, 4, tptc + 512, sv);

    // 4) per-batch stats
    stats_kernel<<<Bb, 256>>>(sv, fv, av, Sb, Qb);

    // 5) GCN layer 1
    gemm_mma_kernel<<<gH, 256, GEMM_SMEM_BYTES>>>(x, Dd, whi+OW0, wlo+OW0, 512, 0,
                                                  nullptr, y, Hh, 512, 0, nullptr, nullptr);
    zero_kernel<<<(2 * Bb * Hh + 255) / 256, 256>>>(pq, 2 * Bb * Hh);
    pq_kernel<<<dim3(Bb, 8), 256>>>(y, av, fv, pv, qv);
    gcn_epilogue_kernel<<<(Mrows * Hh) / 256, 256>>>(y, pv, qv, av, fv, Sb, Qb, gcn_b0, g1, x, h, 0);

    // 6) GCN layer 2: Y2 = x @ W1[:512] + g1 @ W1[512:]
    gemm_mma_kernel<<<gH, 256, GEMM_SMEM_BYTES>>>(x,  Dd, whi+OW1, wlo+OW1, 768, 0,
                                                  nullptr, y, Hh, 512, 0, nullptr, nullptr);
    gemm_mma_kernel<<<gH, 256, GEMM_SMEM_BYTES>>>(g1, Hh, whi+OW1, wlo+OW1, 768, 512,
                                                  nullptr, y, Hh, 256, 2, nullptr, nullptr);
    zero_kernel<<<(2 * Bb * Hh + 255) / 256, 256>>>(pq, 2 * Bb * Hh);
    pq_kernel<<<dim3(Bb, 8), 256>>>(y, av, fv, pv, qv);
    gcn_epilogue_kernel<<<(Mrows * Hh) / 256, 256>>>(y, pv, qv, av, fv, Sb, Qb, gcn_b1, g2, x, h, Hh);

    // 7) out = h @ out_w + out_b  (h built in the two epilogues above)
    gemm_mma_kernel<<<gD, 256, GEMM_SMEM_BYTES>>>(h, Dd, whi+OOUT, wlo+OOUT, 512, 0,
                                                  out_b, out, Dd, 512, 0, nullptr, nullptr);
}

// round 14
// speedup vs baseline: 2.4058x; 1.1420x over previous
#include <cuda_runtime.h>
#include <cuda_bf16.h>
#include <math.h>
#include <stdint.h>

#define Bb   16
#define Nn   1024
#define Dd   512
#define Hh   256
#define Mrows (Bb*Nn)   // 16384
#define XN   (Mrows*Dd) // 8388608

// ---------------- scratch (static device globals; no allocation) ----------------
__device__ float g_tptc[Mrows*1024];            // fp32, only tc half (cols 512+) actually written
__device__ float g_y [Mrows*Hh];
__device__ float g_f [Mrows];
__device__ float g_sv[Mrows];
__device__ float g_a [Mrows];
__device__ float g_S [Bb];
__device__ float g_Q [Bb];
__device__ float g_pq[2*Bb*Hh];
__device__ float g_bias[1024];                  // concat(tp_b, tc_b)

// split-bf16 activations
__device__ __nv_bfloat16 g_xhi[XN],  g_xlo[XN];          // x        [M,512]
__device__ __nv_bfloat16 g_tphi[XN], g_tplo[XN];         // tp       [M,512]
__device__ __nv_bfloat16 g_g1hi[Mrows*Hh], g_g1lo[Mrows*Hh]; // g1   [M,256]
__device__ __nv_bfloat16 g_hhi[XN],  g_hlo[XN];          // h        [M,512]

// split-bf16 weights, transposed to [N, K] row-major
#define WTOT 1376256
__device__ __nv_bfloat16 g_whi[WTOT];
__device__ __nv_bfloat16 g_wlo[WTOT];
#define OTP   0
#define OTC   262144
#define OBIL  524288
#define OW0   786432        // 256 x 512
#define OW1   917504        // 256 x 768
#define OOUT  1114112       // 512 x 512

// ================= helpers =================
__device__ __forceinline__ uint32_t smem_to_u32(const void* p) {
    uint32_t a;
    asm("{ .reg .u64 t; cvta.to.shared.u64 t, %1; cvt.u32.u64 %0, t; }" : "=r"(a) : "l"(p));
    return a;
}
__device__ __forceinline__ float bf_hi(float x) {
    return __bfloat162float(__float2bfloat16(x));
}

#define LDSM4(r, addr) \
    asm volatile("ldmatrix.sync.aligned.m8n8.x4.shared.b16 {%0,%1,%2,%3}, [%4];" \
        : "=r"((r)[0]), "=r"((r)[1]), "=r"((r)[2]), "=r"((r)[3]) : "r"(addr))

#define MMA_BF16(c, a, b0, b1) \
    asm volatile("mma.sync.aligned.m16n8k16.row.col.f32.bf16.bf16.f32 " \
        "{%0,%1,%2,%3}, {%4,%5,%6,%7}, {%8,%9}, {%0,%1,%2,%3};" \
        : "+f"((c)[0]), "+f"((c)[1]), "+f"((c)[2]), "+f"((c)[3]) \
        : "r"((a)[0]), "r"((a)[1]), "r"((a)[2]), "r"((a)[3]), "r"(b0), "r"(b1))

#define CP_ASYNC16(dst, src) \
    asm volatile("cp.async.cg.shared.global [%0], [%1], 16;" :: "r"(dst), "l"(src))
#define CP_COMMIT() asm volatile("cp.async.commit_group;" ::: "memory")
#define CP_WAIT0()  asm volatile("cp.async.wait_group 0;" ::: "memory")

// ================= merged prep: 6 weight splits + bias concat + x split =========
__device__ __forceinline__ void split_one(const float* __restrict__ W,
                                          __nv_bfloat16* __restrict__ hi,
                                          __nv_bfloat16* __restrict__ lo,
                                          int local, int K, int N)
{
    int k = local / N, n = local % N;
    float v = W[local];
    __nv_bfloat16 h = __float2bfloat16(v);
    hi[(size_t)n * K + k] = h;
    lo[(size_t)n * K + k] = __float2bfloat16(v - __bfloat162float(h));
}

__global__ void prep_all_kernel(const float* __restrict__ tp_w, const float* __restrict__ tc_w,
                                const float* __restrict__ bil_w, const float* __restrict__ w0,
                                const float* __restrict__ w1, const float* __restrict__ ow,
                                const float* __restrict__ tp_b, const float* __restrict__ tc_b,
                                const float* __restrict__ x,
                                __nv_bfloat16* __restrict__ hi, __nv_bfloat16* __restrict__ lo,
                                float* __restrict__ bias,
                                __nv_bfloat16* __restrict__ xhi, __nv_bfloat16* __restrict__ xlo)
{
    int idx = blockIdx.x * blockDim.x + threadIdx.x;
    if (idx < 262144)            split_one(tp_w,  hi+OTP,  lo+OTP,  idx,           512, 512);
    else if (idx < 524288)       split_one(tc_w,  hi+OTC,  lo+OTC,  idx - 262144,  512, 512);
    else if (idx < 786432)       split_one(bil_w, hi+OBIL, lo+OBIL, idx - 524288,  512, 512);
    else if (idx < 917504)       split_one(w0,    hi+OW0,  lo+OW0,  idx - 786432,  512, 256);
    else if (idx < 1114112)      split_one(w1,    hi+OW1,  lo+OW1,  idx - 917504,  768, 256);
    else if (idx < 1376256)      split_one(ow,    hi+OOUT, lo+OOUT, idx - 1114112, 512, 512);
    else if (idx < 1376768)      bias[idx - 1376256] = tp_b[idx - 1376256];
    else if (idx < 1377280)      bias[idx - 1376256] = tc_b[idx - 1376768];
    else if (idx < 1377280 + XN) {
        int l = idx - 1377280;
        float v = x[l];
        __nv_bfloat16 h = __float2bfloat16(v);
        xhi[l] = h;
        xlo[l] = __float2bfloat16(v - __bfloat162float(h));
    }
}

// ================= warp-MMA split-bf16 GEMM (pure cp.async loaders) =============
// C = epi(A @ B^T); A pre-split bf16 (Ahi/Alo [M,lda]); B pre-split bf16 [N,ldb].
// flags: bit0 tanh, bit1 accumulate, bit2 dot-epilogue.
// splitLim: cols < splitLim also written as bf16 hi/lo to Chi/Clo (ld = ldsp).
// f32Min:   cols >= f32Min written fp32 to C.
#define LDBF 40
#define AH_OFF 0
#define AL_OFF 10240
#define BH_OFF 20480
#define BL_OFF 30720
#define STG    40960
#define GEMM_SMEM_BYTES (2*STG)

__global__ __launch_bounds__(256, 2) void gemm_mma_kernel(
    const __nv_bfloat16* __restrict__ Ahi, const __nv_bfloat16* __restrict__ Alo, int lda,
    const __nv_bfloat16* __restrict__ Bhi, const __nv_bfloat16* __restrict__ Blo,
    int ldb, int bk0,
    const float* __restrict__ bias,
    float* __restrict__ C, int ldc,
    int K, int flags,
    const float* __restrict__ dotB, float* __restrict__ dotOut,
    __nv_bfloat16* __restrict__ Chi, __nv_bfloat16* __restrict__ Clo, int ldsp,
    int splitLim, int f32Min)
{
    extern __shared__ __align__(16) char smem[];
    const uint32_t sbase = smem_to_u32(smem);

    const int tid  = threadIdx.x;
    const int lane = tid & 31;
    const int wid  = tid >> 5;
    const int wm   = wid & 3;
    const int wn   = wid >> 2;
    const int rowBase = blockIdx.y * 128;
    const int colBase = blockIdx.x * 128;
    const int KT = K >> 5;

    // loader: thread t -> row t/2, 16-elem (32B) half = (t&1)*16
    const int lrow = tid >> 1;
    const int lcol = (tid & 1) * 16;
    const __nv_bfloat16* Agh = Ahi + (size_t)(rowBase + lrow) * lda + lcol;
    const __nv_bfloat16* Agl = Alo + (size_t)(rowBase + lrow) * lda + lcol;
    const __nv_bfloat16* Bgh = Bhi + (size_t)(colBase + lrow) * ldb + bk0 + lcol;
    const __nv_bfloat16* Bgl = Blo + (size_t)(colBase + lrow) * ldb + bk0 + lcol;
    const uint32_t sRow = sbase + (uint32_t)(lrow * LDBF + lcol) * 2;

    uint32_t aoff[2];
    #pragma unroll
    for (int mi = 0; mi < 2; mi++) {
        int r = wm * 32 + mi * 16 + (lane & 15);
        aoff[mi] = (uint32_t)(r * LDBF + (lane >> 4) * 8) * 2;
    }
    uint32_t boff[4];
    {
        int tile = lane >> 3;
        #pragma unroll
        for (int g = 0; g < 4; g++) {
            int n = wn * 64 + g * 16 + (tile >> 1) * 8 + (lane & 7);
            boff[g] = (uint32_t)(n * LDBF + (tile & 1) * 8) * 2 + BH_OFF;
        }
    }

    float acc[2][8][4];
    #pragma unroll
    for (int mi = 0; mi < 2; mi++)
        #pragma unroll
        for (int nf = 0; nf < 8; nf++)
            #pragma unroll
            for (int r = 0; r < 4; r++) acc[mi][nf][r] = 0.0f;

    auto cp_tile = [&](int kt, int s) {
        const uint32_t so = (uint32_t)s * STG;
        const int ko = kt * 32;
        CP_ASYNC16(sRow + so + AH_OFF,      Agh + ko);
        CP_ASYNC16(sRow + so + AH_OFF + 16, Agh + ko + 8);
        CP_ASYNC16(sRow + so + AL_OFF,      Agl + ko);
        CP_ASYNC16(sRow + so + AL_OFF + 16, Agl + ko + 8);
        CP_ASYNC16(sRow + so + BH_OFF,      Bgh + ko);
        CP_ASYNC16(sRow + so + BH_OFF + 16, Bgh + ko + 8);
        CP_ASYNC16(sRow + so + BL_OFF,      Bgl + ko);
        CP_ASYNC16(sRow + so + BL_OFF + 16, Bgl + ko + 8);
        CP_COMMIT();
    };
    auto compute = [&](int s) {
        uint32_t so = sbase + (uint32_t)s * STG;
        #pragma unroll
        for (int ks = 0; ks < 2; ks++) {
            uint32_t kb = (uint32_t)(ks * 16) * 2;
            uint32_t ah[2][4], al[2][4];
            #pragma unroll
            for (int mi = 0; mi < 2; mi++) {
                LDSM4(ah[mi], so + AH_OFF + aoff[mi] + kb);
                LDSM4(al[mi], so + AL_OFF + aoff[mi] + kb);
            }
            #pragma unroll
            for (int g = 0; g < 4; g++) {
                uint32_t bh[4], bl[4];
                LDSM4(bh, so + boff[g] + kb);
                LDSM4(bl, so + boff[g] + kb + (BL_OFF - BH_OFF));
                #pragma unroll
                for (int mi = 0; mi < 2; mi++) {
                    #pragma unroll
                    for (int sub = 0; sub < 2; sub++) {
                        float* c = acc[mi][g * 2 + sub];
                        MMA_BF16(c, ah[mi], bh[2*sub], bh[2*sub+1]);
                        MMA_BF16(c, ah[mi], bl[2*sub], bl[2*sub+1]);
                        MMA_BF16(c, al[mi], bh[2*sub], bh[2*sub+1]);
                    }
                }
            }
        }
    };

    // pipeline: loads for kt+1 overlap compute of kt
    cp_tile(0, 0);
    CP_WAIT0();
    __syncthreads();
    for (int kt = 0; kt < KT; kt++) {
        if (kt + 1 < KT) cp_tile(kt + 1, (kt + 1) & 1);
        compute(kt & 1);
        CP_WAIT0();
        __syncthreads();
    }

    // ---- epilogues
    if (flags & 4) {
        #pragma unroll
        for (int mi = 0; mi < 2; mi++) {
            #pragma unroll
            for (int h = 0; h < 2; h++) {
                int row = rowBase + wm * 32 + mi * 16 + (lane >> 2) + h * 8;
                const float* tb = dotB + (size_t)row * ldc + colBase + wn * 64;
                float p = 0.0f;
                #pragma unroll
                for (int nf = 0; nf < 8; nf++) {
                    int c = nf * 8 + (lane & 3) * 2;
                    float2 t = *reinterpret_cast<const float2*>(tb + c);
                    p += acc[mi][nf][h * 2 + 0] * t.x + acc[mi][nf][h * 2 + 1] * t.y;
                }
                p += __shfl_xor_sync(0xffffffffu, p, 1);
                p += __shfl_xor_sync(0xffffffffu, p, 2);
                if ((lane & 3) == 0) atomicAdd(dotOut + row, p);
            }
        }
        return;
    }
    const bool do_tanh = flags & 1, do_acc = flags & 2;
    #pragma unroll
    for (int mi = 0; mi < 2; mi++) {
        #pragma unroll
        for (int nf = 0; nf < 8; nf++) {
            int row = rowBase + wm * 32 + mi * 16 + (lane >> 2);
            int col = colBase + wn * 64 + nf * 8 + (lane & 3) * 2;
            float* c = acc[mi][nf];
            #pragma unroll
            for (int h = 0; h < 2; h++) {
                int r = row + h * 8;
                float vx = c[h * 2 + 0], vy = c[h * 2 + 1];
                if (do_acc) {
                    float2 o = *reinterpret_cast<const float2*>(C + (size_t)r * ldc + col);
                    vx += o.x; vy += o.y;
                }
                if (bias)   { vx += bias[col]; vy += bias[col + 1]; }
                if (do_tanh){ vx = tanhf(vx); vy = tanhf(vy); }
                if (col < splitLim) {
                    __nv_bfloat16 hx = __float2bfloat16(vx), hy = __float2bfloat16(vy);
                    __nv_bfloat162 hv; hv.x = hx; hv.y = hy;
                    __nv_bfloat162 lv;
                    lv.x = __float2bfloat16(vx - __bfloat162float(hx));
                    lv.y = __float2bfloat16(vy - __bfloat162float(hy));
                    *reinterpret_cast<__nv_bfloat162*>(Chi + (size_t)r * ldsp + col) = hv;
                    *reinterpret_cast<__nv_bfloat162*>(Clo + (size_t)r * ldsp + col) = lv;
                }
                if (col >= f32Min) {
                    float2 v; v.x = vx; v.y = vy;
                    *reinterpret_cast<float2*>(C + (size_t)r * ldc + col) = v;
                }
            }
        }
    }
}

// ================= elementwise / reduction kernels =================
__global__ void rowdot_exp_kernel(const float* __restrict__ x,
                                  const float* __restrict__ w,
                                  float* __restrict__ out,
                                  float* __restrict__ svz, int K)
{
    int row  = blockIdx.x * 8 + (threadIdx.x >> 5);
    int lane = threadIdx.x & 31;
    const float* xr = x + (size_t)row * K;
    float s = 0.0f;
    for (int k = lane; k < K; k += 32) s += xr[k] * w[k];
    #pragma unroll
    for (int o = 16; o > 0; o >>= 1) s += __shfl_xor_sync(0xffffffffu, s, o);
    if (lane == 0) { out[row] = expf(s); svz[row] = 0.0f; }
}

__global__ void stats_kernel(const float* __restrict__ s,
                             const float* __restrict__ f,
                             float* __restrict__ a,
                             float* __restrict__ Sb, float* __restrict__ Qb)
{
    __shared__ float red[256];
    int b = blockIdx.x;
    int t = threadIdx.x;
    const float* sb = s + b * Nn;
    const float* fb = f + b * Nn;
    float* ab = a + b * Nn;

    float mx = -1e30f;
    for (int i = t; i < Nn; i += 256) mx = fmaxf(mx, sb[i]);
    red[t] = mx; __syncthreads();
    for (int off = 128; off > 0; off >>= 1) {
        if (t < off) red[t] = fmaxf(red[t], red[t + off]);
        __syncthreads();
    }
    mx = red[0]; __syncthreads();

    float ls = 0.0f, lq = 0.0f;
    for (int i = t; i < Nn; i += 256) {
        float av = expf(sb[i] - mx);
        ab[i] = av;
        ls += av;
        lq += av * fb[i];
    }
    red[t] = ls; __syncthreads();
    for (int off = 128; off > 0; off >>= 1) {
        if (t < off) red[t] += red[t + off];
        __syncthreads();
    }
    float S = red[0]; __syncthreads();
    red[t] = lq; __syncthreads();
    for (int off = 128; off > 0; off >>= 1) {
        if (t < off) red[t] += red[t + off];
        __syncthreads();
    }
    if (t == 0) { Sb[b] = S; Qb[b] = red[0]; }
}

__global__ void zero_kernel(float* __restrict__ p, int n)
{
    int i = blockIdx.x * blockDim.x + threadIdx.x;
    if (i < n) p[i] = 0.0f;
}

__global__ void pq_kernel(const float* __restrict__ Y,
                          const float* __restrict__ a,
                          const float* __restrict__ f,
                          float* __restrict__ p, float* __restrict__ q)
{
    int b = blockIdx.x;
    int chunk = blockIdx.y;
    int e = threadIdx.x;
    const float* Yb = Y + ((size_t)b * Nn + chunk * 128) * Hh;
    const float* ab = a + b * Nn + chunk * 128;
    const float* fb = f + b * Nn + chunk * 128;
    float lp = 0.0f, lq = 0.0f;
    for (int n = 0; n < 128; n++) {
        float av = ab[n];
        float y  = Yb[(size_t)n * Hh + e];
        lp += av * y;
        lq += av * fb[n] * y;
    }
    atomicAdd(&p[b * Hh + e], lp);
    atomicAdd(&q[b * Hh + e], lq);
}

// GCN epilogue: computes g; writes split-bf16 g (optional) and split-bf16 h-half = g + x
__global__ void gcn_epilogue_kernel(const float* __restrict__ Y,
                                    const float* __restrict__ p,
                                    const float* __restrict__ q,
                                    const float* __restrict__ a,
                                    const float* __restrict__ f,
                                    const float* __restrict__ Sb,
                                    const float* __restrict__ Qb,
                                    const float* __restrict__ bias,
                                    const float* __restrict__ x,
                                    __nv_bfloat16* __restrict__ ghi,
                                    __nv_bfloat16* __restrict__ glo,
                                    __nv_bfloat16* __restrict__ hhi,
                                    __nv_bfloat16* __restrict__ hlo, int colOff)
{
    int idx = blockIdx.x * blockDim.x + threadIdx.x;
    int e = idx & (Hh - 1);
    int m = idx >> 8;
    int b = m >> 10;
    float am = a[m], fm = f[m];
    float S = Sb[b], Q = Qb[b];
    float t = am * fm / Q;
    float y = Y[idx];
    float adjy = ((1.0f - t) * p[b * Hh + e] + (am / Q) * q[b * Hh + e] - am * y) / S;
    float v = (adjy + y + 2.0f * bias[e]) / (2.0f - t);
    float g = fmaxf(v, 0.0f);
    if (ghi) {
        __nv_bfloat16 gh = __float2bfloat16(g);
        ghi[idx] = gh;
        glo[idx] = __float2bfloat16(g - __bfloat162float(gh));
    }
    size_t hx = (size_t)m * Dd + colOff + e;
    float hv = g + x[hx];
    __nv_bfloat16 hh = __float2bfloat16(hv);
    hhi[hx] = hh;
    hlo[hx] = __float2bfloat16(hv - __bfloat162float(hh));
}

// ================= launcher =================
extern "C" void kernel_launch(void* const* d_in, const int* in_sizes, int n_in,
                              void* d_out, int out_size)
{
    const float* x      = (const float*)d_in[0];
    const float* tp_w   = (const float*)d_in[1];
    const float* tp_b   = (const float*)d_in[2];
    const float* tc_w   = (const float*)d_in[3];
    const float* tc_b   = (const float*)d_in[4];
    const float* fi_w   = (const float*)d_in[5];
    const float* bil_w  = (const float*)d_in[6];
    const float* gcn_w0 = (const float*)d_in[7];
    const float* gcn_b0 = (const float*)d_in[8];
    const float* gcn_w1 = (const float*)d_in[9];
    const float* gcn_b1 = (const float*)d_in[10];
    const float* out_w  = (const float*)d_in[11];
    const float* out_b  = (const float*)d_in[12];
    float* out = (float*)d_out;

    float *tptc, *y, *fv, *sv, *av, *Sb, *Qb, *pq, *cbias;
    __nv_bfloat16 *whi, *wlo, *xhi, *xlo, *tphi, *tplo, *g1hi, *g1lo, *hhi, *hlo;
    cudaGetSymbolAddress((void**)&tptc, g_tptc);
    cudaGetSymbolAddress((void**)&y,  g_y);
    cudaGetSymbolAddress((void**)&fv, g_f);
    cudaGetSymbolAddress((void**)&sv, g_sv);
    cudaGetSymbolAddress((void**)&av, g_a);
    cudaGetSymbolAddress((void**)&Sb, g_S);
    cudaGetSymbolAddress((void**)&Qb, g_Q);
    cudaGetSymbolAddress((void**)&pq, g_pq);
    cudaGetSymbolAddress((void**)&cbias, g_bias);
    cudaGetSymbolAddress((void**)&whi, g_whi);
    cudaGetSymbolAddress((void**)&wlo, g_wlo);
    cudaGetSymbolAddress((void**)&xhi, g_xhi);
    cudaGetSymbolAddress((void**)&xlo, g_xlo);
    cudaGetSymbolAddress((void**)&tphi, g_tphi);
    cudaGetSymbolAddress((void**)&tplo, g_tplo);
    cudaGetSymbolAddress((void**)&g1hi, g_g1hi);
    cudaGetSymbolAddress((void**)&g1lo, g_g1lo);
    cudaGetSymbolAddress((void**)&hhi, g_hhi);
    cudaGetSymbolAddress((void**)&hlo, g_hlo);
    float* pv = pq;
    float* qv = pq + Bb * Hh;

    cudaFuncSetAttribute(gemm_mma_kernel, cudaFuncAttributeMaxDynamicSharedMemorySize, GEMM_SMEM_BYTES);

    // 0) merged prep: 6 weight splits + bias concat + x split — one launch
    prep_all_kernel<<<(1377280 + XN + 255) / 256, 256>>>(
        tp_w, tc_w, bil_w, gcn_w0, gcn_w1, out_w, tp_b, tc_b, x, whi, wlo, cbias, xhi, xlo);

    dim3 gTT(1024 / 128, Mrows / 128);
    dim3 gD(Dd / 128, Mrows / 128);
    dim3 gH(Hh / 128, Mrows / 128);

    // 1) [tp|tc] = tanh(x@[tp_w|tc_w]+bias): tp (cols<512) -> split bf16 only; tc -> fp32 only
    gemm_mma_kernel<<<gTT, 256, GEMM_SMEM_BYTES>>>(xhi, xlo, 512, whi+OTP, wlo+OTP, 512, 0,
        cbias, tptc, 1024, 512, 1, nullptr, nullptr, tphi, tplo, 512, 512, 512);

    // 2) f = exp(x @ fi_w); zero sv
    rowdot_exp_kernel<<<Mrows / 8, 256>>>(x, fi_w, fv, sv, Dd);

    // 3) s = rowdot(tp @ bil_w, tc) — dot fused, u never materialized
    gemm_mma_kernel<<<gD, 256, GEMM_SMEM_BYTES>>>(tphi, tplo, 512, whi+OBIL, wlo+OBIL, 512, 0,
        nullptr, nullptr, 1024, 512, 4, tptc + 512, sv, nullptr, nullptr, 0, 0, 0);

    // 4) per-batch stats
    stats_kernel<<<Bb, 256>>>(sv, fv, av, Sb, Qb);

    // 5) GCN layer 1
    gemm_mma_kernel<<<gH, 256, GEMM_SMEM_BYTES>>>(xhi, xlo, 512, whi+OW0, wlo+OW0, 512, 0,
        nullptr, y, Hh, 512, 0, nullptr, nullptr, nullptr, nullptr, 0, 0, 0);
    zero_kernel<<<(2 * Bb * Hh + 255) / 256, 256>>>(pq, 2 * Bb * Hh);
    pq_kernel<<<dim3(Bb, 8), 256>>>(y, av, fv, pv, qv);
    gcn_epilogue_kernel<<<(Mrows * Hh) / 256, 256>>>(y, pv, qv, av, fv, Sb, Qb, gcn_b0, x,
                                                     g1hi, g1lo, hhi, hlo, 0);

    // 6) GCN layer 2: Y2 = x @ W1[:512] + g1 @ W1[512:]
    gemm_mma_kernel<<<gH, 256, GEMM_SMEM_BYTES>>>(xhi, xlo, 512, whi+OW1, wlo+OW1, 768, 0,
        nullptr, y, Hh, 512, 0, nullptr, nullptr, nullptr, nullptr, 0, 0, 0);
    gemm_mma_kernel<<<gH, 256, GEMM_SMEM_BYTES>>>(g1hi, g1lo, 256, whi+OW1, wlo+OW1, 768, 512,
        nullptr, y, Hh, 256, 2, nullptr, nullptr, nullptr, nullptr, 0, 0, 0);
    zero_kernel<<<(2 * Bb * Hh + 255) / 256, 256>>>(pq, 2 * Bb * Hh);
    pq_kernel<<<dim3(Bb, 8), 256>>>(y, av, fv, pv, qv);
    gcn_epilogue_kernel<<<(Mrows * Hh) / 256, 256>>>(y, pv, qv, av, fv, Sb, Qb, gcn_b1, x,
                                                     nullptr, nullptr, hhi, hlo, Hh);

    // 7) out = h @ out_w + out_b
    gemm_mma_kernel<<<gD, 256, GEMM_SMEM_BYTES>>>(hhi, hlo, 512, whi+OOUT, wlo+OOUT, 512, 0,
        out_b, out, Dd, 512, 0, nullptr, nullptr, nullptr, nullptr, 0, 0, 0);
}

// round 15
// speedup vs baseline: 2.4182x; 1.0052x over previous
#include <cuda_runtime.h>
#include <cuda_bf16.h>
#include <math.h>
#include <stdint.h>

#define Bb   16
#define Nn   1024
#define Dd   512
#define Hh   256
#define Mrows (Bb*Nn)   // 16384
#define XN   (Mrows*Dd) // 8388608

// ---------------- scratch (static device globals; no allocation) ----------------
__device__ float g_tptc[Mrows*1024];            // fp32, only tc half (cols 512+) actually written
__device__ float g_y [Mrows*Hh];
__device__ float g_f [Mrows];
__device__ float g_sv[Mrows];
__device__ float g_a [Mrows];
__device__ float g_S [Bb];
__device__ float g_Q [Bb];
__device__ float g_pq[2*Bb*Hh];
__device__ float g_bias[1024];                  // concat(tp_b, tc_b)

// split-bf16 activations
__device__ __nv_bfloat16 g_xhi[XN],  g_xlo[XN];
__device__ __nv_bfloat16 g_tphi[XN], g_tplo[XN];
__device__ __nv_bfloat16 g_g1hi[Mrows*Hh], g_g1lo[Mrows*Hh];
__device__ __nv_bfloat16 g_hhi[XN],  g_hlo[XN];

// split-bf16 weights, transposed to [N, K] row-major
#define WTOT 1376256
__device__ __nv_bfloat16 g_whi[WTOT];
__device__ __nv_bfloat16 g_wlo[WTOT];
#define OTP   0
#define OTC   262144
#define OBIL  524288
#define OW0   786432
#define OW1   917504
#define OOUT  1114112

// ================= helpers =================
__device__ __forceinline__ uint32_t smem_to_u32(const void* p) {
    uint32_t a;
    asm("{ .reg .u64 t; cvta.to.shared.u64 t, %1; cvt.u32.u64 %0, t; }" : "=r"(a) : "l"(p));
    return a;
}

#define LDSM4(r, addr) \
    asm volatile("ldmatrix.sync.aligned.m8n8.x4.shared.b16 {%0,%1,%2,%3}, [%4];" \
        : "=r"((r)[0]), "=r"((r)[1]), "=r"((r)[2]), "=r"((r)[3]) : "r"(addr))

#define MMA_BF16(c, a, b0, b1) \
    asm volatile("mma.sync.aligned.m16n8k16.row.col.f32.bf16.bf16.f32 " \
        "{%0,%1,%2,%3}, {%4,%5,%6,%7}, {%8,%9}, {%0,%1,%2,%3};" \
        : "+f"((c)[0]), "+f"((c)[1]), "+f"((c)[2]), "+f"((c)[3]) \
        : "r"((a)[0]), "r"((a)[1]), "r"((a)[2]), "r"((a)[3]), "r"(b0), "r"(b1))

#define CP_ASYNC16(dst, src) \
    asm volatile("cp.async.cg.shared.global [%0], [%1], 16;" :: "r"(dst), "l"(src))
#define CP_COMMIT() asm volatile("cp.async.commit_group;" ::: "memory")
#define CP_WAIT0()  asm volatile("cp.async.wait_group 0;" ::: "memory")

// ================= merged prep =================
__device__ __forceinline__ void split_one(const float* __restrict__ W,
                                          __nv_bfloat16* __restrict__ hi,
                                          __nv_bfloat16* __restrict__ lo,
                                          int local, int K, int N)
{
    int k = local / N, n = local % N;
    float v = W[local];
    __nv_bfloat16 h = __float2bfloat16(v);
    hi[(size_t)n * K + k] = h;
    lo[(size_t)n * K + k] = __float2bfloat16(v - __bfloat162float(h));
}

__global__ void prep_all_kernel(const float* __restrict__ tp_w, const float* __restrict__ tc_w,
                                const float* __restrict__ bil_w, const float* __restrict__ w0,
                                const float* __restrict__ w1, const float* __restrict__ ow,
                                const float* __restrict__ tp_b, const float* __restrict__ tc_b,
                                const float* __restrict__ x,
                                __nv_bfloat16* __restrict__ hi, __nv_bfloat16* __restrict__ lo,
                                float* __restrict__ bias,
                                __nv_bfloat16* __restrict__ xhi, __nv_bfloat16* __restrict__ xlo)
{
    int idx = blockIdx.x * blockDim.x + threadIdx.x;
    if (idx < 262144)            split_one(tp_w,  hi+OTP,  lo+OTP,  idx,           512, 512);
    else if (idx < 524288)       split_one(tc_w,  hi+OTC,  lo+OTC,  idx - 262144,  512, 512);
    else if (idx < 786432)       split_one(bil_w, hi+OBIL, lo+OBIL, idx - 524288,  512, 512);
    else if (idx < 917504)       split_one(w0,    hi+OW0,  lo+OW0,  idx - 786432,  512, 256);
    else if (idx < 1114112)      split_one(w1,    hi+OW1,  lo+OW1,  idx - 917504,  768, 256);
    else if (idx < 1376256)      split_one(ow,    hi+OOUT, lo+OOUT, idx - 1114112, 512, 512);
    else if (idx < 1376768)      bias[idx - 1376256] = tp_b[idx - 1376256];
    else if (idx < 1377280)      bias[idx - 1376256] = tc_b[idx - 1376768];
    else if (idx < 1377280 + XN) {
        int l = idx - 1377280;
        float v = x[l];
        __nv_bfloat16 h = __float2bfloat16(v);
        xhi[l] = h;
        xlo[l] = __float2bfloat16(v - __bfloat162float(h));
    }
}

// ================= warp-MMA split-bf16 GEMM =================
#define LDBF 40
#define AH_OFF 0
#define AL_OFF 10240
#define BH_OFF 20480
#define BL_OFF 30720
#define STG    40960
#define GEMM_SMEM_BYTES (2*STG)

__global__ __launch_bounds__(256, 2) void gemm_mma_kernel(
    const __nv_bfloat16* __restrict__ Ahi, const __nv_bfloat16* __restrict__ Alo, int lda,
    const __nv_bfloat16* __restrict__ Bhi, const __nv_bfloat16* __restrict__ Blo,
    int ldb, int bk0,
    const float* __restrict__ bias,
    float* __restrict__ C, int ldc,
    int K, int flags,
    const float* __restrict__ dotB, float* __restrict__ dotOut,
    __nv_bfloat16* __restrict__ Chi, __nv_bfloat16* __restrict__ Clo, int ldsp,
    int splitLim, int f32Min)
{
    extern __shared__ __align__(16) char smem[];
    const uint32_t sbase = smem_to_u32(smem);

    const int tid  = threadIdx.x;
    const int lane = tid & 31;
    const int wid  = tid >> 5;
    const int wm   = wid & 3;
    const int wn   = wid >> 2;
    const int rowBase = blockIdx.y * 128;
    const int colBase = blockIdx.x * 128;
    const int KT = K >> 5;

    const int lrow = tid >> 1;
    const int lcol = (tid & 1) * 16;
    const __nv_bfloat16* Agh = Ahi + (size_t)(rowBase + lrow) * lda + lcol;
    const __nv_bfloat16* Agl = Alo + (size_t)(rowBase + lrow) * lda + lcol;
    const __nv_bfloat16* Bgh = Bhi + (size_t)(colBase + lrow) * ldb + bk0 + lcol;
    const __nv_bfloat16* Bgl = Blo + (size_t)(colBase + lrow) * ldb + bk0 + lcol;
    const uint32_t sRow = sbase + (uint32_t)(lrow * LDBF + lcol) * 2;

    uint32_t aoff[2];
    #pragma unroll
    for (int mi = 0; mi < 2; mi++) {
        int r = wm * 32 + mi * 16 + (lane & 15);
        aoff[mi] = (uint32_t)(r * LDBF + (lane >> 4) * 8) * 2;
    }
    uint32_t boff[4];
    {
        int tile = lane >> 3;
        #pragma unroll
        for (int g = 0; g < 4; g++) {
            int n = wn * 64 + g * 16 + (tile >> 1) * 8 + (lane & 7);
            boff[g] = (uint32_t)(n * LDBF + (tile & 1) * 8) * 2 + BH_OFF;
        }
    }

    float acc[2][8][4];
    #pragma unroll
    for (int mi = 0; mi < 2; mi++)
        #pragma unroll
        for (int nf = 0; nf < 8; nf++)
            #pragma unroll
            for (int r = 0; r < 4; r++) acc[mi][nf][r] = 0.0f;

    auto cp_tile = [&](int kt, int s) {
        const uint32_t so = (uint32_t)s * STG;
        const int ko = kt * 32;
        CP_ASYNC16(sRow + so + AH_OFF,      Agh + ko);
        CP_ASYNC16(sRow + so + AH_OFF + 16, Agh + ko + 8);
        CP_ASYNC16(sRow + so + AL_OFF,      Agl + ko);
        CP_ASYNC16(sRow + so + AL_OFF + 16, Agl + ko + 8);
        CP_ASYNC16(sRow + so + BH_OFF,      Bgh + ko);
        CP_ASYNC16(sRow + so + BH_OFF + 16, Bgh + ko + 8);
        CP_ASYNC16(sRow + so + BL_OFF,      Bgl + ko);
        CP_ASYNC16(sRow + so + BL_OFF + 16, Bgl + ko + 8);
        CP_COMMIT();
    };

    // compute: product-pass reordered (4 independent MMAs between same-acc reuse)
    // + register double-buffered B fragments across the g-loop.
    auto compute = [&](int s) {
        uint32_t so = sbase + (uint32_t)s * STG;
        #pragma unroll
        for (int ks = 0; ks < 2; ks++) {
            uint32_t kb = (uint32_t)(ks * 16) * 2;
            uint32_t ah[2][4], al[2][4];
            #pragma unroll
            for (int mi = 0; mi < 2; mi++) {
                LDSM4(ah[mi], so + AH_OFF + aoff[mi] + kb);
                LDSM4(al[mi], so + AL_OFF + aoff[mi] + kb);
            }
            uint32_t bh[2][4], bl[2][4];
            LDSM4(bh[0], so + boff[0] + kb);
            LDSM4(bl[0], so + boff[0] + kb + (BL_OFF - BH_OFF));
            #pragma unroll
            for (int g = 0; g < 4; g++) {
                const int cur = g & 1, nxt = cur ^ 1;
                if (g < 3) {
                    LDSM4(bh[nxt], so + boff[g + 1] + kb);
                    LDSM4(bl[nxt], so + boff[g + 1] + kb + (BL_OFF - BH_OFF));
                }
                // pass 1: Ah x Bh — 4 independent accumulators
                #pragma unroll
                for (int mi = 0; mi < 2; mi++)
                    #pragma unroll
                    for (int sub = 0; sub < 2; sub++)
                        MMA_BF16(acc[mi][g * 2 + sub], ah[mi], bh[cur][2*sub], bh[cur][2*sub+1]);
                // pass 2: Ah x Bl
                #pragma unroll
                for (int mi = 0; mi < 2; mi++)
                    #pragma unroll
                    for (int sub = 0; sub < 2; sub++)
                        MMA_BF16(acc[mi][g * 2 + sub], ah[mi], bl[cur][2*sub], bl[cur][2*sub+1]);
                // pass 3: Al x Bh
                #pragma unroll
                for (int mi = 0; mi < 2; mi++)
                    #pragma unroll
                    for (int sub = 0; sub < 2; sub++)
                        MMA_BF16(acc[mi][g * 2 + sub], al[mi], bh[cur][2*sub], bh[cur][2*sub+1]);
            }
        }
    };

    cp_tile(0, 0);
    CP_WAIT0();
    __syncthreads();
    for (int kt = 0; kt < KT; kt++) {
        if (kt + 1 < KT) cp_tile(kt + 1, (kt + 1) & 1);
        compute(kt & 1);
        CP_WAIT0();
        __syncthreads();
    }

    // ---- epilogues
    if (flags & 4) {
        #pragma unroll
        for (int mi = 0; mi < 2; mi++) {
            #pragma unroll
            for (int h = 0; h < 2; h++) {
                int row = rowBase + wm * 32 + mi * 16 + (lane >> 2) + h * 8;
                const float* tb = dotB + (size_t)row * ldc + colBase + wn * 64;
                float p = 0.0f;
                #pragma unroll
                for (int nf = 0; nf < 8; nf++) {
                    int c = nf * 8 + (lane & 3) * 2;
                    float2 t = *reinterpret_cast<const float2*>(tb + c);
                    p += acc[mi][nf][h * 2 + 0] * t.x + acc[mi][nf][h * 2 + 1] * t.y;
                }
                p += __shfl_xor_sync(0xffffffffu, p, 1);
                p += __shfl_xor_sync(0xffffffffu, p, 2);
                if ((lane & 3) == 0) atomicAdd(dotOut + row, p);
            }
        }
        return;
    }
    const bool do_tanh = flags & 1, do_acc = flags & 2;
    #pragma unroll
    for (int mi = 0; mi < 2; mi++) {
        #pragma unroll
        for (int nf = 0; nf < 8; nf++) {
            int row = rowBase + wm * 32 + mi * 16 + (lane >> 2);
            int col = colBase + wn * 64 + nf * 8 + (lane & 3) * 2;
            float* c = acc[mi][nf];
            #pragma unroll
            for (int h = 0; h < 2; h++) {
                int r = row + h * 8;
                float vx = c[h * 2 + 0], vy = c[h * 2 + 1];
                if (do_acc) {
                    float2 o = *reinterpret_cast<const float2*>(C + (size_t)r * ldc + col);
                    vx += o.x; vy += o.y;
                }
                if (bias)   { vx += bias[col]; vy += bias[col + 1]; }
                if (do_tanh){ vx = tanhf(vx); vy = tanhf(vy); }
                if (col < splitLim) {
                    __nv_bfloat16 hx = __float2bfloat16(vx), hy = __float2bfloat16(vy);
                    __nv_bfloat162 hv; hv.x = hx; hv.y = hy;
                    __nv_bfloat162 lv;
                    lv.x = __float2bfloat16(vx - __bfloat162float(hx));
                    lv.y = __float2bfloat16(vy - __bfloat162float(hy));
                    *reinterpret_cast<__nv_bfloat162*>(Chi + (size_t)r * ldsp + col) = hv;
                    *reinterpret_cast<__nv_bfloat162*>(Clo + (size_t)r * ldsp + col) = lv;
                }
                if (col >= f32Min) {
                    float2 v; v.x = vx; v.y = vy;
                    *reinterpret_cast<float2*>(C + (size_t)r * ldc + col) = v;
                }
            }
        }
    }
}

// ================= elementwise / reduction kernels =================
__global__ void rowdot_exp_kernel(const float* __restrict__ x,
                                  const float* __restrict__ w,
                                  float* __restrict__ out,
                                  float* __restrict__ svz, int K)
{
    int row  = blockIdx.x * 8 + (threadIdx.x >> 5);
    int lane = threadIdx.x & 31;
    const float* xr = x + (size_t)row * K;
    float s = 0.0f;
    for (int k = lane; k < K; k += 32) s += xr[k] * w[k];
    #pragma unroll
    for (int o = 16; o > 0; o >>= 1) s += __shfl_xor_sync(0xffffffffu, s, o);
    if (lane == 0) { out[row] = expf(s); svz[row] = 0.0f; }
}

__global__ void stats_kernel(const float* __restrict__ s,
                             const float* __restrict__ f,
                             float* __restrict__ a,
                             float* __restrict__ Sb, float* __restrict__ Qb)
{
    __shared__ float red[256];
    int b = blockIdx.x;
    int t = threadIdx.x;
    const float* sb = s + b * Nn;
    const float* fb = f + b * Nn;
    float* ab = a + b * Nn;

    float mx = -1e30f;
    for (int i = t; i < Nn; i += 256) mx = fmaxf(mx, sb[i]);
    red[t] = mx; __syncthreads();
    for (int off = 128; off > 0; off >>= 1) {
        if (t < off) red[t] = fmaxf(red[t], red[t + off]);
        __syncthreads();
    }
    mx = red[0]; __syncthreads();

    float ls = 0.0f, lq = 0.0f;
    for (int i = t; i < Nn; i += 256) {
        float av = expf(sb[i] - mx);
        ab[i] = av;
        ls += av;
        lq += av * fb[i];
    }
    red[t] = ls; __syncthreads();
    for (int off = 128; off > 0; off >>= 1) {
        if (t < off) red[t] += red[t + off];
        __syncthreads();
    }
    float S = red[0]; __syncthreads();
    red[t] = lq; __syncthreads();
    for (int off = 128; off > 0; off >>= 1) {
        if (t < off) red[t] += red[t + off];
        __syncthreads();
    }
    if (t == 0) { Sb[b] = S; Qb[b] = red[0]; }
}

__global__ void zero_kernel(float* __restrict__ p, int n)
{
    int i = blockIdx.x * blockDim.x + threadIdx.x;
    if (i < n) p[i] = 0.0f;
}

__global__ void pq_kernel(const float* __restrict__ Y,
                          const float* __restrict__ a,
                          const float* __restrict__ f,
                          float* __restrict__ p, float* __restrict__ q)
{
    int b = blockIdx.x;
    int chunk = blockIdx.y;
    int e = threadIdx.x;
    const float* Yb = Y + ((size_t)b * Nn + chunk * 128) * Hh;
    const float* ab = a + b * Nn + chunk * 128;
    const float* fb = f + b * Nn + chunk * 128;
    float lp = 0.0f, lq = 0.0f;
    for (int n = 0; n < 128; n++) {
        float av = ab[n];
        float y  = Yb[(size_t)n * Hh + e];
        lp += av * y;
        lq += av * fb[n] * y;
    }
    atomicAdd(&p[b * Hh + e], lp);
    atomicAdd(&q[b * Hh + e], lq);
}

__global__ void gcn_epilogue_kernel(const float* __restrict__ Y,
                                    const float* __restrict__ p,
                                    const float* __restrict__ q,
                                    const float* __restrict__ a,
                                    const float* __restrict__ f,
                                    const float* __restrict__ Sb,
                                    const float* __restrict__ Qb,
                                    const float* __restrict__ bias,
                                    const float* __restrict__ x,
                                    __nv_bfloat16* __restrict__ ghi,
                                    __nv_bfloat16* __restrict__ glo,
                                    __nv_bfloat16* __restrict__ hhi,
                                    __nv_bfloat16* __restrict__ hlo, int colOff)
{
    int idx = blockIdx.x * blockDim.x + threadIdx.x;
    int e = idx & (Hh - 1);
    int m = idx >> 8;
    int b = m >> 10;
    float am = a[m], fm = f[m];
    float S = Sb[b], Q = Qb[b];
    float t = am * fm / Q;
    float y = Y[idx];
    float adjy = ((1.0f - t) * p[b * Hh + e] + (am / Q) * q[b * Hh + e] - am * y) / S;
    float v = (adjy + y + 2.0f * bias[e]) / (2.0f - t);
    float g = fmaxf(v, 0.0f);
    if (ghi) {
        __nv_bfloat16 gh = __float2bfloat16(g);
        ghi[idx] = gh;
        glo[idx] = __float2bfloat16(g - __bfloat162float(gh));
    }
    size_t hx = (size_t)m * Dd + colOff + e;
    float hv = g + x[hx];
    __nv_bfloat16 hh = __float2bfloat16(hv);
    hhi[hx] = hh;
    hlo[hx] = __float2bfloat16(hv - __bfloat162float(hh));
}

// ================= launcher =================
extern "C" void kernel_launch(void* const* d_in, const int* in_sizes, int n_in,
                              void* d_out, int out_size)
{
    const float* x      = (const float*)d_in[0];
    const float* tp_w   = (const float*)d_in[1];
    const float* tp_b   = (const float*)d_in[2];
    const float* tc_w   = (const float*)d_in[3];
    const float* tc_b   = (const float*)d_in[4];
    const float* fi_w   = (const float*)d_in[5];
    const float* bil_w  = (const float*)d_in[6];
    const float* gcn_w0 = (const float*)d_in[7];
    const float* gcn_b0 = (const float*)d_in[8];
    const float* gcn_w1 = (const float*)d_in[9];
    const float* gcn_b1 = (const float*)d_in[10];
    const float* out_w  = (const float*)d_in[11];
    const float* out_b  = (const float*)d_in[12];
    float* out = (float*)d_out;

    float *tptc, *y, *fv, *sv, *av, *Sb, *Qb, *pq, *cbias;
    __nv_bfloat16 *whi, *wlo, *xhi, *xlo, *tphi, *tplo, *g1hi, *g1lo, *hhi, *hlo;
    cudaGetSymbolAddress((void**)&tptc, g_tptc);
    cudaGetSymbolAddress((void**)&y,  g_y);
    cudaGetSymbolAddress((void**)&fv, g_f);
    cudaGetSymbolAddress((void**)&sv, g_sv);
    cudaGetSymbolAddress((void**)&av, g_a);
    cudaGetSymbolAddress((void**)&Sb, g_S);
    cudaGetSymbolAddress((void**)&Qb, g_Q);
    cudaGetSymbolAddress((void**)&pq, g_pq);
    cudaGetSymbolAddress((void**)&cbias, g_bias);
    cudaGetSymbolAddress((void**)&whi, g_whi);
    cudaGetSymbolAddress((void**)&wlo, g_wlo);
    cudaGetSymbolAddress((void**)&xhi, g_xhi);
    cudaGetSymbolAddress((void**)&xlo, g_xlo);
    cudaGetSymbolAddress((void**)&tphi, g_tphi);
    cudaGetSymbolAddress((void**)&tplo, g_tplo);
    cudaGetSymbolAddress((void**)&g1hi, g_g1hi);
    cudaGetSymbolAddress((void**)&g1lo, g_g1lo);
    cudaGetSymbolAddress((void**)&hhi, g_hhi);
    cudaGetSymbolAddress((void**)&hlo, g_hlo);
    float* pv = pq;
    float* qv = pq + Bb * Hh;

    cudaFuncSetAttribute(gemm_mma_kernel, cudaFuncAttributeMaxDynamicSharedMemorySize, GEMM_SMEM_BYTES);

    // 0) merged prep
    prep_all_kernel<<<(1377280 + XN + 255) / 256, 256>>>(
        tp_w, tc_w, bil_w, gcn_w0, gcn_w1, out_w, tp_b, tc_b, x, whi, wlo, cbias, xhi, xlo);

    dim3 gTT(1024 / 128, Mrows / 128);
    dim3 gD(Dd / 128, Mrows / 128);
    dim3 gH(Hh / 128, Mrows / 128);

    // 1) [tp|tc] = tanh(x@[tp_w|tc_w]+bias): tp -> split bf16; tc -> fp32
    gemm_mma_kernel<<<gTT, 256, GEMM_SMEM_BYTES>>>(xhi, xlo, 512, whi+OTP, wlo+OTP, 512, 0,
        cbias, tptc, 1024, 512, 1, nullptr, nullptr, tphi, tplo, 512, 512, 512);

    // 2) f = exp(x @ fi_w); zero sv
    rowdot_exp_kernel<<<Mrows / 8, 256>>>(x, fi_w, fv, sv, Dd);

    // 3) s = rowdot(tp @ bil_w, tc)
    gemm_mma_kernel<<<gD, 256, GEMM_SMEM_BYTES>>>(tphi, tplo, 512, whi+OBIL, wlo+OBIL, 512, 0,
        nullptr, nullptr, 1024, 512, 4, tptc + 512, sv, nullptr, nullptr, 0, 0, 0);

    // 4) per-batch stats
    stats_kernel<<<Bb, 256>>>(sv, fv, av, Sb, Qb);

    // 5) GCN layer 1
    gemm_mma_kernel<<<gH, 256, GEMM_SMEM_BYTES>>>(xhi, xlo, 512, whi+OW0, wlo+OW0, 512, 0,
        nullptr, y, Hh, 512, 0, nullptr, nullptr, nullptr, nullptr, 0, 0, 0);
    zero_kernel<<<(2 * Bb * Hh + 255) / 256, 256>>>(pq, 2 * Bb * Hh);
    pq_kernel<<<dim3(Bb, 8), 256>>>(y, av, fv, pv, qv);
    gcn_epilogue_kernel<<<(Mrows * Hh) / 256, 256>>>(y, pv, qv, av, fv, Sb, Qb, gcn_b0, x,
                                                     g1hi, g1lo, hhi, hlo, 0);

    // 6) GCN layer 2
    gemm_mma_kernel<<<gH, 256, GEMM_SMEM_BYTES>>>(xhi, xlo, 512, whi+OW1, wlo+OW1, 768, 0,
        nullptr, y, Hh, 512, 0, nullptr, nullptr, nullptr, nullptr, 0, 0, 0);
    gemm_mma_kernel<<<gH, 256, GEMM_SMEM_BYTES>>>(g1hi, g1lo, 256, whi+OW1, wlo+OW1, 768, 512,
        nullptr, y, Hh, 256, 2, nullptr, nullptr, nullptr, nullptr, 0, 0, 0);
    zero_kernel<<<(2 * Bb * Hh + 255) / 256, 256>>>(pq, 2 * Bb * Hh);
    pq_kernel<<<dim3(Bb, 8), 256>>>(y, av, fv, pv, qv);
    gcn_epilogue_kernel<<<(Mrows * Hh) / 256, 256>>>(y, pv, qv, av, fv, Sb, Qb, gcn_b1, x,
                                                     nullptr, nullptr, hhi, hlo, Hh);

    // 7) out = h @ out_w + out_b
    gemm_mma_kernel<<<gD, 256, GEMM_SMEM_BYTES>>>(hhi, hlo, 512, whi+OOUT, wlo+OOUT, 512, 0,
        out_b, out, Dd, 512, 0, nullptr, nullptr, nullptr, nullptr, 0, 0, 0);
}